// round 10
// baseline (speedup 1.0000x reference)
#include <cuda_runtime.h>
#include <cuda_bf16.h>
#include <cstdint>

// Problem constants
#define VOCAB  32000
#define EMBED  100
#define HID    128
#define BATCH  1024
#define SEQ    256

// -------- device scratch (no allocation allowed) --------
__device__ __align__(16) float g_P[VOCAB * HID];            // fused projections (16.4 MB)
__device__ __align__(16) __nv_bfloat16 g_Ehi[VOCAB * 128];  // emb split (padded K=128)
__device__ __align__(16) __nv_bfloat16 g_Elo[VOCAB * 128];
__device__ __align__(16) __nv_bfloat16 g_Whi[VOCAB * 128];  // W_fc split
__device__ __align__(16) __nv_bfloat16 g_Wlo[VOCAB * 128];
__device__ __align__(16) __nv_bfloat16 g_IHhi[128 * 128];   // W_ih split
__device__ __align__(16) __nv_bfloat16 g_IHlo[128 * 128];
__device__ __align__(16) __nv_bfloat16 g_WHhi[128 * 128];   // W_hh split
__device__ __align__(16) __nv_bfloat16 g_WHlo[128 * 128];
__device__ __align__(16) __nv_bfloat16 g_Hhi[BATCH * 128];  // h_last split
__device__ __align__(16) __nv_bfloat16 g_Hlo[BATCH * 128];

// ============================================================================
// Pre-split conversion: fp32 [rows][Kv] -> hi/lo bf16 [rows][128] (zero-pad).
// ============================================================================
__global__ void __launch_bounds__(256) k_cvt(
    const float* __restrict__ src, int Kv,
    __nv_bfloat16* __restrict__ hi, __nv_bfloat16* __restrict__ lo)
{
    const int r    = blockIdx.x * 8 + (threadIdx.x >> 5);
    const int lane = threadIdx.x & 31;
    #pragma unroll
    for (int cp = lane; cp < 64; cp += 32) {
        const int c0 = 2 * cp;
        float a = (c0     < Kv) ? src[(long long)r * Kv + c0]     : 0.0f;
        float b = (c0 + 1 < Kv) ? src[(long long)r * Kv + c0 + 1] : 0.0f;
        __nv_bfloat16 ha = __float2bfloat16_rn(a), hb = __float2bfloat16_rn(b);
        __nv_bfloat16 la = __float2bfloat16_rn(a - __bfloat162float(ha));
        __nv_bfloat16 lb = __float2bfloat16_rn(b - __bfloat162float(hb));
        ((uint32_t*)hi)[r * 64 + cp] = (uint32_t)*(uint16_t*)&ha | ((uint32_t)*(uint16_t*)&hb << 16);
        ((uint32_t*)lo)[r * 64 + cp] = (uint32_t)*(uint16_t*)&la | ((uint32_t)*(uint16_t*)&lb << 16);
    }
}

// ============================================================================
// mma.sync helpers (validated in passing rounds)
// ============================================================================
__device__ __forceinline__ uint32_t smem_u32(const void* p) {
    uint32_t a;
    asm("{ .reg .u64 t; cvta.to.shared.u64 t, %1; cvt.u32.u64 %0, t; }" : "=r"(a) : "l"(p));
    return a;
}
__device__ __forceinline__ void ldmx4(uint32_t* r, uint32_t a) {
    asm volatile("ldmatrix.sync.aligned.m8n8.x4.shared.b16 {%0,%1,%2,%3}, [%4];"
                 : "=r"(r[0]), "=r"(r[1]), "=r"(r[2]), "=r"(r[3]) : "r"(a));
}
__device__ __forceinline__ void ldmx2(uint32_t* r, uint32_t a) {
    asm volatile("ldmatrix.sync.aligned.m8n8.x2.shared.b16 {%0,%1}, [%2];"
                 : "=r"(r[0]), "=r"(r[1]) : "r"(a));
}
__device__ __forceinline__ void mma_bf16(float* c, const uint32_t* a,
                                         uint32_t b0, uint32_t b1) {
    asm volatile("mma.sync.aligned.m16n8k16.row.col.f32.bf16.bf16.f32 "
                 "{%0,%1,%2,%3}, {%4,%5,%6,%7}, {%8,%9}, {%0,%1,%2,%3};"
                 : "+f"(c[0]), "+f"(c[1]), "+f"(c[2]), "+f"(c[3])
                 : "r"(a[0]), "r"(a[1]), "r"(a[2]), "r"(a[3]), "r"(b0), "r"(b1));
}
__device__ __forceinline__ uint32_t tswz(int row, int u) {
    return (uint32_t)(row * 256 + ((u ^ (row & 7)) << 4));
}
__device__ __forceinline__ void load_tile(const __nv_bfloat16* __restrict__ g,
                                          char* s, int rows, int tid) {
    #pragma unroll 4
    for (int i = tid; i < rows * 16; i += 256) {
        int row = i >> 4, u = i & 15;
        *(uint4*)(s + tswz(row, u)) = *(const uint4*)(g + (long long)row * 128 + u * 8);
    }
}
__device__ __forceinline__ float fast_tanh(float x) {
    float e = __expf(2.0f * x);
    return 1.0f - __fdividef(2.0f, e + 1.0f);
}
__device__ __forceinline__ uint32_t pack_hi(float a, float b, uint32_t& lo_out) {
    __nv_bfloat16 ha = __float2bfloat16_rn(a), hb = __float2bfloat16_rn(b);
    __nv_bfloat16 la = __float2bfloat16_rn(a - __bfloat162float(ha));
    __nv_bfloat16 lb = __float2bfloat16_rn(b - __bfloat162float(hb));
    lo_out = (uint32_t)*(uint16_t*)&la | ((uint32_t)*(uint16_t*)&lb << 16);
    return (uint32_t)*(uint16_t*)&ha | ((uint32_t)*(uint16_t*)&hb << 16);
}
__device__ __forceinline__ uint32_t mapa_peer(uint32_t addr, uint32_t rank) {
    uint32_t r;
    asm("mapa.shared::cluster.u32 %0, %1, %2;" : "=r"(r) : "r"(addr), "r"(rank));
    return r;
}
__device__ __forceinline__ uint32_t my_cluster_rank() {
    uint32_t r;
    asm("mov.u32 %0, %%cluster_ctarank;" : "=r"(r));
    return r;
}
#define CLUSTER_SYNC() do { \
    asm volatile("barrier.cluster.arrive.aligned;" ::: "memory"); \
    asm volatile("barrier.cluster.wait.aligned;" ::: "memory"); } while (0)
#define MBAR_INIT(a, c) \
    asm volatile("mbarrier.init.shared.b64 [%0], %1;" :: "r"(a), "r"(c) : "memory")
#define MBAR_ARRIVE_LOCAL(a) \
    asm volatile("mbarrier.arrive.release.cluster.shared::cta.b64 _, [%0];" :: "r"(a) : "memory")
#define MBAR_ARRIVE_REMOTE(a) \
    asm volatile("mbarrier.arrive.release.cluster.shared::cluster.b64 _, [%0];" :: "r"(a) : "memory")
#define ST_CLUSTER_U32(a, v) \
    asm volatile("st.shared::cluster.u32 [%0], %1;" :: "r"(a), "r"(v) : "memory")
__device__ __forceinline__ void mbar_wait_acq(uint32_t mbar, uint32_t parity) {
    uint32_t done;
    asm volatile("{\n\t.reg .pred p;\n\t"
                 "mbarrier.try_wait.parity.acquire.cluster.shared::cta.b64 p, [%1], %2;\n\t"
                 "selp.b32 %0, 1, 0, p;\n\t}" : "=r"(done) : "r"(mbar), "r"(parity) : "memory");
    if (!done) {
        asm volatile("{\n\t.reg .pred P1;\n\tWL%=:\n\t"
                     "mbarrier.try_wait.parity.acquire.cluster.shared::cta.b64 P1, [%0], %1;\n\t"
                     "@P1 bra.uni WD%=;\n\tbra.uni WL%=;\n\tWD%=:\n\t}"
                     :: "r"(mbar), "r"(parity) : "memory");
    }
}

// ============================================================================
// GEMM: block tile 128M x 64N, K=128, 8 warps (4M x 2N of 32x32), occ 2.
// (unchanged from round 7/9 passing version)
// ============================================================================
#define A_TILE 32768
#define B_TILE 16384
#define GEMM_SMEM (2 * A_TILE + 2 * B_TILE)   // 98304
#define EPAD 68

__global__ void __launch_bounds__(256, 2) k_gemm(
    const __nv_bfloat16* __restrict__ Ahi_g, const __nv_bfloat16* __restrict__ Alo_g,
    const __nv_bfloat16* __restrict__ Bhi_g, const __nv_bfloat16* __restrict__ Blo_g,
    float* __restrict__ out, long long ldout,
    const float* __restrict__ bias1, const float* __restrict__ bias2)
{
    extern __shared__ __align__(16) char sm[];
    __shared__ float sbias[64];
    char* Ahi = sm;
    char* Alo = sm + A_TILE;
    char* Bhi = sm + 2 * A_TILE;
    char* Blo = sm + 2 * A_TILE + B_TILE;

    const int tid = threadIdx.x, w = tid >> 5, lane = tid & 31;
    const int wm = w >> 1, wn = w & 1;
    const int m0 = blockIdx.x * 128, n0 = blockIdx.y * 64;

    load_tile(Ahi_g + (long long)m0 * 128, Ahi, 128, tid);
    load_tile(Alo_g + (long long)m0 * 128, Alo, 128, tid);
    load_tile(Bhi_g + (long long)n0 * 128, Bhi, 64, tid);
    load_tile(Blo_g + (long long)n0 * 128, Blo, 64, tid);
    if (tid < 64) sbias[tid] = bias1[n0 + tid] + (bias2 ? bias2[n0 + tid] : 0.0f);
    __syncthreads();

    const int sw = lane & 7;
    const int arow = wm * 32 + (lane & 15);
    const int akh  = lane >> 4;
    const int brow = wn * 32 + (lane & 7) + 8 * (lane >> 4);
    const int bkh  = (lane >> 3) & 1;

    const uint32_t sA0h = smem_u32(Ahi) + arow * 256;
    const uint32_t sA0l = smem_u32(Alo) + arow * 256;
    const uint32_t sB0h = smem_u32(Bhi) + brow * 256;
    const uint32_t sB0l = smem_u32(Blo) + brow * 256;

    float acc[2][4][4];
    #pragma unroll
    for (int mt = 0; mt < 2; mt++)
        #pragma unroll
        for (int nt = 0; nt < 4; nt++)
            #pragma unroll
            for (int q = 0; q < 4; q++) acc[mt][nt][q] = 0.0f;

    #pragma unroll
    for (int ks = 0; ks < 8; ks++) {
        const uint32_t uA = (uint32_t)(((2 * ks + akh) ^ sw) << 4);
        const uint32_t uB = (uint32_t)(((2 * ks + bkh) ^ sw) << 4);
        uint32_t aHi[2][4], aLo[2][4];
        ldmx4(aHi[0], sA0h + uA);
        ldmx4(aHi[1], sA0h + 16 * 256 + uA);
        ldmx4(aLo[0], sA0l + uA);
        ldmx4(aLo[1], sA0l + 16 * 256 + uA);
        #pragma unroll
        for (int np = 0; np < 2; np++) {
            uint32_t bh[4], bl[4];
            ldmx4(bh, sB0h + np * 16 * 256 + uB);
            ldmx4(bl, sB0l + np * 16 * 256 + uB);
            #pragma unroll
            for (int mt = 0; mt < 2; mt++) {
                mma_bf16(acc[mt][2 * np],     aHi[mt], bh[0], bh[1]);
                mma_bf16(acc[mt][2 * np + 1], aHi[mt], bh[2], bh[3]);
                mma_bf16(acc[mt][2 * np],     aLo[mt], bh[0], bh[1]);
                mma_bf16(acc[mt][2 * np + 1], aLo[mt], bh[2], bh[3]);
                mma_bf16(acc[mt][2 * np],     aHi[mt], bl[0], bl[1]);
                mma_bf16(acc[mt][2 * np + 1], aHi[mt], bl[2], bl[3]);
            }
        }
    }

    __syncthreads();
    float* stg = (float*)sm;
    const int g = lane >> 2, tig = lane & 3;
    #pragma unroll
    for (int mt = 0; mt < 2; mt++) {
        const int r0 = wm * 32 + mt * 16 + g;
        #pragma unroll
        for (int nt = 0; nt < 4; nt++) {
            const int col = wn * 32 + nt * 8 + 2 * tig;
            *(float2*)(stg + r0 * EPAD + col)       = make_float2(acc[mt][nt][0], acc[mt][nt][1]);
            *(float2*)(stg + (r0 + 8) * EPAD + col) = make_float2(acc[mt][nt][2], acc[mt][nt][3]);
        }
    }
    __syncthreads();
    #pragma unroll 4
    for (int i = tid; i < 128 * 16; i += 256) {
        const int row = i >> 4, u = i & 15, col = u * 4;
        float4 v = *(const float4*)(stg + row * EPAD + col);
        v.x += sbias[col]; v.y += sbias[col + 1]; v.z += sbias[col + 2]; v.w += sbias[col + 3];
        *(float4*)(out + (long long)(m0 + row) * ldout + n0 + col) = v;
    }
}

// ============================================================================
// Kernel B: cluster-of-2 MMA RNN scan. 128 CTAs (64 clusters) x 256 threads.
// Cluster owns 16 batch rows; rank r computes cols j in [64r, 64r+64) — 8
// warps x n8 = 24 HMMA/warp/step (half the 64-CTA version's per-SMSP load,
// spread over 2x the SMs). h tile (16 rows x 128 cols, hi/lo, double-buffered)
// is replicated per CTA: epilogue writes each packed value locally AND to the
// peer via mapa + st.shared::cluster. Per-step sync = one 512-count mbarrier
// per CTA (local arrive + remote arrive, release.cluster; parity try_wait).
// W_hh fragments preloaded into registers (zero B LDSM in steady state).
// ============================================================================
#define SXP 260
#define S2_OFF_W    0                         // W rows (local 64): hi 16KB + lo 16KB
#define S2_OFF_AT   32768                     // AT + buf*8192 + hilo*4096 (16KB)
#define S2_OFF_SX   49152                     // 16 x SXP ints
#define S2_OFF_MBAR (S2_OFF_SX + 16 * SXP * 4)
#define S2_SMEM     (S2_OFF_MBAR + 32)

__global__ void __launch_bounds__(256, 1) __cluster_dims__(2, 1, 1)
k_rnn_cluster(const int* __restrict__ x)
{
    extern __shared__ __align__(16) char sm[];
    char* WHhi = sm + S2_OFF_W;
    char* WHlo = sm + S2_OFF_W + 16384;
    char* AT   = sm + S2_OFF_AT;
    int*  sx   = (int*)(sm + S2_OFF_SX);

    const int tid = threadIdx.x, w = tid >> 5, lane = tid & 31;
    const uint32_t rank = my_cluster_rank();
    const uint32_t peer = rank ^ 1;
    const int b0 = (blockIdx.x >> 1) * 16;
    const uint32_t mbar = smem_u32(sm) + S2_OFF_MBAR;

    // prologue: local W half, x stage, zero h buffer 0, mbar init
    load_tile(g_WHhi + (long long)rank * 64 * 128, WHhi, 64, tid);
    load_tile(g_WHlo + (long long)rank * 64 * 128, WHlo, 64, tid);
    for (int i = tid; i < 16 * SEQ; i += 256) {
        int row = i >> 8, t = i & 255;
        sx[row * SXP + t] = x[(b0 + row) * SEQ + t];
    }
    for (int i = tid; i < 512; i += 256)
        ((uint4*)AT)[i] = make_uint4(0, 0, 0, 0);
    if (tid == 0) MBAR_INIT(mbar, 512);
    __syncthreads();

    // preload B fragments (W_hh local rows w*8..w*8+8, full K) — static
    const int l15 = lane & 15;
    const int browB = w * 8 + (l15 & 7);
    const int bkh   = (l15 >> 3) & 1;
    const int swB   = l15 & 7;
    const uint32_t sBh = smem_u32(WHhi) + browB * 256;
    const uint32_t sBl = smem_u32(WHlo) + browB * 256;
    uint32_t bfh[8][2], bfl[8][2];
    #pragma unroll
    for (int ks = 0; ks < 8; ks++) {
        const uint32_t uB = (uint32_t)(((2 * ks + bkh) ^ swB) << 4);
        ldmx2(bfh[ks], sBh + uB);
        ldmx2(bfl[ks], sBl + uB);
    }

    // A-frag addressing
    const int arow = lane & 15;
    const int akh  = lane >> 4;
    const int swA  = lane & 7;
    const uint32_t sAT = smem_u32(AT);
    const uint32_t aH0 = sAT + arow * 256;          // + buf*8192 (+4096 for lo)

    // epilogue addressing: thread owns rows g, g+8; cols jc = rank*64+w*8+2*tig
    const int g = lane >> 2, tig = lane & 3;
    const int jc = (int)rank * 64 + w * 8 + 2 * tig;
    const int ustore = (int)rank * 8 + w;           // 16B unit of this col pair
    uint32_t st0 = (uint32_t)(g * 256 + ((ustore ^ (g & 7)) << 4) + 4 * tig);
    uint32_t st1 = (uint32_t)((g + 8) * 256 + ((ustore ^ ((g + 8) & 7)) << 4) + 4 * tig);

    // mbar init of both CTAs must complete before any remote traffic
    CLUSTER_SYNC();
    const uint32_t mbar_peer = mapa_peer(mbar, peer);

    int cur = 0;
    for (int t = 0; t < SEQ; t++) {
        // P gather (consumed post-MMA; L2 latency hides under MMA)
        const int idx0 = sx[g * SXP + t];
        const int idx1 = sx[(g + 8) * SXP + t];
        const float2 p0 = *(const float2*)(g_P + idx0 * HID + jc);
        const float2 p1 = *(const float2*)(g_P + idx1 * HID + jc);

        float aH[4] = {0, 0, 0, 0}, aM[4] = {0, 0, 0, 0}, aL[4] = {0, 0, 0, 0};
        const uint32_t aAddrH = aH0 + cur * 8192;
        const uint32_t aAddrL = aAddrH + 4096;
        #pragma unroll
        for (int ks = 0; ks < 8; ks++) {
            const uint32_t uA = (uint32_t)(((2 * ks + akh) ^ swA) << 4);
            uint32_t ahi[4], alo[4];
            ldmx4(ahi, aAddrH + uA);
            ldmx4(alo, aAddrL + uA);
            mma_bf16(aH, ahi, bfh[ks][0], bfh[ks][1]);
            mma_bf16(aM, ahi, bfl[ks][0], bfl[ks][1]);
            mma_bf16(aL, alo, bfh[ks][0], bfh[ks][1]);
        }

        // epilogue: v = mma + P; h = tanh(v); split; store local + peer
        const int nxt = cur ^ 1;
        const uint32_t dHi = sAT + nxt * 8192;
        const uint32_t dLo = dHi + 4096;
        const float h00 = fast_tanh(aH[0] + aM[0] + aL[0] + p0.x);
        const float h01 = fast_tanh(aH[1] + aM[1] + aL[1] + p0.y);
        const float h10 = fast_tanh(aH[2] + aM[2] + aL[2] + p1.x);
        const float h11 = fast_tanh(aH[3] + aM[3] + aL[3] + p1.y);
        uint32_t lo0, lo1;
        const uint32_t hi0 = pack_hi(h00, h01, lo0);
        const uint32_t hi1 = pack_hi(h10, h11, lo1);
        *(uint32_t*)(sm + (dHi - smem_u32(sm)) + st0) = hi0;
        *(uint32_t*)(sm + (dHi - smem_u32(sm)) + st1) = hi1;
        *(uint32_t*)(sm + (dLo - smem_u32(sm)) + st0) = lo0;
        *(uint32_t*)(sm + (dLo - smem_u32(sm)) + st1) = lo1;
        ST_CLUSTER_U32(mapa_peer(dHi + st0, peer), hi0);
        ST_CLUSTER_U32(mapa_peer(dHi + st1, peer), hi1);
        ST_CLUSTER_U32(mapa_peer(dLo + st0, peer), lo0);
        ST_CLUSTER_U32(mapa_peer(dLo + st1, peer), lo1);

        // sync: both CTAs' 256 threads arrive on BOTH mbars; wait local
        MBAR_ARRIVE_LOCAL(mbar);
        MBAR_ARRIVE_REMOTE(mbar_peer);
        mbar_wait_acq(mbar, (uint32_t)(t & 1));
        cur = nxt;
    }

    // write final h (full 128 cols present in local buffer) — rank 0 only
    if (rank == 0) {
        char* Fhi = AT + cur * 8192;
        char* Flo = AT + cur * 8192 + 4096;
        for (int i = tid; i < 16 * 64; i += 256) {
            const int row = i >> 6, cp = i & 63;
            const uint32_t off = (uint32_t)(row * 256 + (((cp >> 2) ^ (row & 7)) << 4) + (cp & 3) * 4);
            ((uint32_t*)g_Hhi)[(b0 + row) * 64 + cp] = *(const uint32_t*)(Fhi + off);
            ((uint32_t*)g_Hlo)[(b0 + row) * 64 + cp] = *(const uint32_t*)(Flo + off);
        }
    }
    CLUSTER_SYNC();   // no CTA exits while peer may still be accessed
}

// ============================================================================
// launch
// ============================================================================
extern "C" void kernel_launch(void* const* d_in, const int* in_sizes, int n_in,
                              void* d_out, int out_size) {
    const int*   x    = (const int*)d_in[0];     // int32: JAX downcasts int64
    const float* emb  = (const float*)d_in[1];
    const float* W_ih = (const float*)d_in[2];
    const float* W_hh = (const float*)d_in[3];
    const float* b_ih = (const float*)d_in[4];
    const float* b_hh = (const float*)d_in[5];
    const float* W_fc = (const float*)d_in[6];
    const float* b_fc = (const float*)d_in[7];
    float*       out  = (float*)d_out;

    static float* P_p = nullptr;
    static __nv_bfloat16 *Ehi_p, *Elo_p, *Whi_p, *Wlo_p, *IHhi_p, *IHlo_p;
    static __nv_bfloat16 *WHhi_p, *WHlo_p, *Hhi_p, *Hlo_p;
    if (!P_p) {
        cudaGetSymbolAddress((void**)&P_p,    g_P);
        cudaGetSymbolAddress((void**)&Ehi_p,  g_Ehi);
        cudaGetSymbolAddress((void**)&Elo_p,  g_Elo);
        cudaGetSymbolAddress((void**)&Whi_p,  g_Whi);
        cudaGetSymbolAddress((void**)&Wlo_p,  g_Wlo);
        cudaGetSymbolAddress((void**)&IHhi_p, g_IHhi);
        cudaGetSymbolAddress((void**)&IHlo_p, g_IHlo);
        cudaGetSymbolAddress((void**)&WHhi_p, g_WHhi);
        cudaGetSymbolAddress((void**)&WHlo_p, g_WHlo);
        cudaGetSymbolAddress((void**)&Hhi_p,  g_Hhi);
        cudaGetSymbolAddress((void**)&Hlo_p,  g_Hlo);
        cudaFuncSetAttribute(k_gemm,        cudaFuncAttributeMaxDynamicSharedMemorySize, GEMM_SMEM);
        cudaFuncSetAttribute(k_rnn_cluster, cudaFuncAttributeMaxDynamicSharedMemorySize, S2_SMEM);
    }

    // pre-split weights/embeddings to hi/lo bf16 (K padded to 128)
    k_cvt<<<VOCAB / 8, 256>>>(emb,  EMBED, Ehi_p,  Elo_p);
    k_cvt<<<HID / 8,   256>>>(W_ih, EMBED, IHhi_p, IHlo_p);
    k_cvt<<<HID / 8,   256>>>(W_hh, HID,   WHhi_p, WHlo_p);
    k_cvt<<<VOCAB / 8, 256>>>(W_fc, HID,   Whi_p,  Wlo_p);

    // P[v][j] = emb[v]·W_ih[j] + (b_ih+b_hh)[j]
    k_gemm<<<dim3(VOCAB / 128, HID / 64), 256, GEMM_SMEM>>>(
        Ehi_p, Elo_p, IHhi_p, IHlo_p, P_p, HID, b_ih, b_hh);

    // recurrent scan on tensor cores, cluster-of-2 (writes g_Hhi/g_Hlo)
    k_rnn_cluster<<<BATCH / 8, 256, S2_SMEM>>>(x);

    // out[b][v] = h[b]·W_fc[v] + b_fc[v]
    k_gemm<<<dim3(BATCH / 128, VOCAB / 64), 256, GEMM_SMEM>>>(
        Hhi_p, Hlo_p, Whi_p, Wlo_p, out, VOCAB, b_fc, nullptr);
}

// round 11
// speedup vs baseline: 1.2947x; 1.2947x over previous
#include <cuda_runtime.h>
#include <cuda_fp16.h>
#include <cstdint>

// Problem constants
#define VOCAB  32000
#define EMBED  100
#define HID    128
#define BATCH  1024
#define SEQ    256

// -------- device scratch (no allocation allowed) --------
__device__ __align__(16) float g_P[VOCAB * HID];        // fused projections (16.4 MB)
__device__ __align__(16) __half g_Ehi[VOCAB * 128];     // emb split (padded K=128)
__device__ __align__(16) __half g_Elo[VOCAB * 128];
__device__ __align__(16) __half g_Whi[VOCAB * 128];     // W_fc split
__device__ __align__(16) __half g_Wlo[VOCAB * 128];
__device__ __align__(16) __half g_IHhi[128 * 128];      // W_ih split
__device__ __align__(16) __half g_IHlo[128 * 128];
__device__ __align__(16) __half g_WHhi[128 * 128];      // W_hh split
__device__ __align__(16) __half g_WHlo[128 * 128];
__device__ __align__(16) __half g_Hhi[BATCH * 128];     // h_last split
__device__ __align__(16) __half g_Hlo[BATCH * 128];

// ============================================================================
// Pre-split conversion: fp32 [rows][Kv] -> hi/lo fp16 [rows][128] (zero-pad).
// fp16 hi captures 12 bits; hi+lo ~22 bits (near-fp32). All tensors here are
// comfortably inside fp16 range (|emb| ~ 4 max, |W| < 0.1, |h| < 1).
// ============================================================================
__global__ void __launch_bounds__(256) k_cvt(
    const float* __restrict__ src, int Kv,
    __half* __restrict__ hi, __half* __restrict__ lo)
{
    const int r    = blockIdx.x * 8 + (threadIdx.x >> 5);
    const int lane = threadIdx.x & 31;
    #pragma unroll
    for (int cp = lane; cp < 64; cp += 32) {
        const int c0 = 2 * cp;
        float a = (c0     < Kv) ? src[(long long)r * Kv + c0]     : 0.0f;
        float b = (c0 + 1 < Kv) ? src[(long long)r * Kv + c0 + 1] : 0.0f;
        __half ha = __float2half_rn(a), hb = __float2half_rn(b);
        __half la = __float2half_rn(a - __half2float(ha));
        __half lb = __float2half_rn(b - __half2float(hb));
        ((uint32_t*)hi)[r * 64 + cp] = (uint32_t)*(uint16_t*)&ha | ((uint32_t)*(uint16_t*)&hb << 16);
        ((uint32_t*)lo)[r * 64 + cp] = (uint32_t)*(uint16_t*)&la | ((uint32_t)*(uint16_t*)&lb << 16);
    }
}

// ============================================================================
// mma.sync helpers (fp16 in / fp32 accum)
// ============================================================================
__device__ __forceinline__ uint32_t smem_u32(const void* p) {
    uint32_t a;
    asm("{ .reg .u64 t; cvta.to.shared.u64 t, %1; cvt.u32.u64 %0, t; }" : "=r"(a) : "l"(p));
    return a;
}
__device__ __forceinline__ void ldmx4(uint32_t* r, uint32_t a) {
    asm volatile("ldmatrix.sync.aligned.m8n8.x4.shared.b16 {%0,%1,%2,%3}, [%4];"
                 : "=r"(r[0]), "=r"(r[1]), "=r"(r[2]), "=r"(r[3]) : "r"(a));
}
__device__ __forceinline__ void mma_f16(float* c, const uint32_t* a,
                                        uint32_t b0, uint32_t b1) {
    asm volatile("mma.sync.aligned.m16n8k16.row.col.f32.f16.f16.f32 "
                 "{%0,%1,%2,%3}, {%4,%5,%6,%7}, {%8,%9}, {%0,%1,%2,%3};"
                 : "+f"(c[0]), "+f"(c[1]), "+f"(c[2]), "+f"(c[3])
                 : "r"(a[0]), "r"(a[1]), "r"(a[2]), "r"(a[3]), "r"(b0), "r"(b1));
}
__device__ __forceinline__ uint32_t tswz(int row, int u) {
    return (uint32_t)(row * 256 + ((u ^ (row & 7)) << 4));
}
__device__ __forceinline__ void load_tile(const __half* __restrict__ g,
                                          char* s, int rows, int tid) {
    #pragma unroll 4
    for (int i = tid; i < rows * 16; i += 256) {
        int row = i >> 4, u = i & 15;
        *(uint4*)(s + tswz(row, u)) = *(const uint4*)(g + (long long)row * 128 + u * 8);
    }
}
__device__ __forceinline__ float fast_tanh(float x) {
    float e = __expf(2.0f * x);
    return 1.0f - __fdividef(2.0f, e + 1.0f);
}
__device__ __forceinline__ uint32_t pack_hi(float a, float b, uint32_t& lo_out) {
    __half ha = __float2half_rn(a), hb = __float2half_rn(b);
    __half la = __float2half_rn(a - __half2float(ha));
    __half lb = __float2half_rn(b - __half2float(hb));
    lo_out = (uint32_t)*(uint16_t*)&la | ((uint32_t)*(uint16_t*)&lb << 16);
    return (uint32_t)*(uint16_t*)&ha | ((uint32_t)*(uint16_t*)&hb << 16);
}

// ============================================================================
// k_gemm: 3-term split GEMM (used for the small P projection).
// Block tile 128M x 64N, K=128, 8 warps (4M x 2N of 32x32), occ 2.
// ============================================================================
#define A_TILE 32768
#define B_TILE 16384
#define GEMM_SMEM (2 * A_TILE + 2 * B_TILE)   // 98304
#define EPAD 68

__global__ void __launch_bounds__(256, 2) k_gemm(
    const __half* __restrict__ Ahi_g, const __half* __restrict__ Alo_g,
    const __half* __restrict__ Bhi_g, const __half* __restrict__ Blo_g,
    float* __restrict__ out, long long ldout,
    const float* __restrict__ bias1, const float* __restrict__ bias2)
{
    extern __shared__ __align__(16) char sm[];
    __shared__ float sbias[64];
    char* Ahi = sm;
    char* Alo = sm + A_TILE;
    char* Bhi = sm + 2 * A_TILE;
    char* Blo = sm + 2 * A_TILE + B_TILE;

    const int tid = threadIdx.x, w = tid >> 5, lane = tid & 31;
    const int wm = w >> 1, wn = w & 1;
    const int m0 = blockIdx.x * 128, n0 = blockIdx.y * 64;

    load_tile(Ahi_g + (long long)m0 * 128, Ahi, 128, tid);
    load_tile(Alo_g + (long long)m0 * 128, Alo, 128, tid);
    load_tile(Bhi_g + (long long)n0 * 128, Bhi, 64, tid);
    load_tile(Blo_g + (long long)n0 * 128, Blo, 64, tid);
    if (tid < 64) sbias[tid] = bias1[n0 + tid] + (bias2 ? bias2[n0 + tid] : 0.0f);
    __syncthreads();

    const int sw = lane & 7;
    const int arow = wm * 32 + (lane & 15);
    const int akh  = lane >> 4;
    const int brow = wn * 32 + (lane & 7) + 8 * (lane >> 4);
    const int bkh  = (lane >> 3) & 1;

    const uint32_t sA0h = smem_u32(Ahi) + arow * 256;
    const uint32_t sA0l = smem_u32(Alo) + arow * 256;
    const uint32_t sB0h = smem_u32(Bhi) + brow * 256;
    const uint32_t sB0l = smem_u32(Blo) + brow * 256;

    float acc[2][4][4];
    #pragma unroll
    for (int mt = 0; mt < 2; mt++)
        #pragma unroll
        for (int nt = 0; nt < 4; nt++)
            #pragma unroll
            for (int q = 0; q < 4; q++) acc[mt][nt][q] = 0.0f;

    #pragma unroll
    for (int ks = 0; ks < 8; ks++) {
        const uint32_t uA = (uint32_t)(((2 * ks + akh) ^ sw) << 4);
        const uint32_t uB = (uint32_t)(((2 * ks + bkh) ^ sw) << 4);
        uint32_t aHi[2][4], aLo[2][4];
        ldmx4(aHi[0], sA0h + uA);
        ldmx4(aHi[1], sA0h + 16 * 256 + uA);
        ldmx4(aLo[0], sA0l + uA);
        ldmx4(aLo[1], sA0l + 16 * 256 + uA);
        #pragma unroll
        for (int np = 0; np < 2; np++) {
            uint32_t bh[4], bl[4];
            ldmx4(bh, sB0h + np * 16 * 256 + uB);
            ldmx4(bl, sB0l + np * 16 * 256 + uB);
            #pragma unroll
            for (int mt = 0; mt < 2; mt++) {
                mma_f16(acc[mt][2 * np],     aHi[mt], bh[0], bh[1]);
                mma_f16(acc[mt][2 * np + 1], aHi[mt], bh[2], bh[3]);
                mma_f16(acc[mt][2 * np],     aLo[mt], bh[0], bh[1]);
                mma_f16(acc[mt][2 * np + 1], aLo[mt], bh[2], bh[3]);
                mma_f16(acc[mt][2 * np],     aHi[mt], bl[0], bl[1]);
                mma_f16(acc[mt][2 * np + 1], aHi[mt], bl[2], bl[3]);
            }
        }
    }

    __syncthreads();
    float* stg = (float*)sm;
    const int g = lane >> 2, tig = lane & 3;
    #pragma unroll
    for (int mt = 0; mt < 2; mt++) {
        const int r0 = wm * 32 + mt * 16 + g;
        #pragma unroll
        for (int nt = 0; nt < 4; nt++) {
            const int col = wn * 32 + nt * 8 + 2 * tig;
            *(float2*)(stg + r0 * EPAD + col)       = make_float2(acc[mt][nt][0], acc[mt][nt][1]);
            *(float2*)(stg + (r0 + 8) * EPAD + col) = make_float2(acc[mt][nt][2], acc[mt][nt][3]);
        }
    }
    __syncthreads();
    #pragma unroll 4
    for (int i = tid; i < 128 * 16; i += 256) {
        const int row = i >> 4, u = i & 15, col = u * 4;
        float4 v = *(const float4*)(stg + row * EPAD + col);
        v.x += sbias[col]; v.y += sbias[col + 1]; v.z += sbias[col + 2]; v.w += sbias[col + 3];
        *(float4*)(out + (long long)(m0 + row) * ldout + n0 + col) = v;
    }
}

// ============================================================================
// k_gemm1: SINGLE-term fp16 GEMM for the head (error budget ~2e-4 spent here;
// 64 MMA/warp instead of 192). smem 48KB -> occ 3.
// ============================================================================
#define G1_SMEM (A_TILE + B_TILE)   // 49152

__global__ void __launch_bounds__(256, 3) k_gemm1(
    const __half* __restrict__ Ahi_g, const __half* __restrict__ Bhi_g,
    float* __restrict__ out, long long ldout, const float* __restrict__ bias1)
{
    extern __shared__ __align__(16) char sm[];
    __shared__ float sbias[64];
    char* Ahi = sm;
    char* Bhi = sm + A_TILE;

    const int tid = threadIdx.x, w = tid >> 5, lane = tid & 31;
    const int wm = w >> 1, wn = w & 1;
    const int m0 = blockIdx.x * 128, n0 = blockIdx.y * 64;

    load_tile(Ahi_g + (long long)m0 * 128, Ahi, 128, tid);
    load_tile(Bhi_g + (long long)n0 * 128, Bhi, 64, tid);
    if (tid < 64) sbias[tid] = bias1[n0 + tid];
    __syncthreads();

    const int sw = lane & 7;
    const int arow = wm * 32 + (lane & 15);
    const int akh  = lane >> 4;
    const int brow = wn * 32 + (lane & 7) + 8 * (lane >> 4);
    const int bkh  = (lane >> 3) & 1;

    const uint32_t sA0h = smem_u32(Ahi) + arow * 256;
    const uint32_t sB0h = smem_u32(Bhi) + brow * 256;

    float acc[2][4][4];
    #pragma unroll
    for (int mt = 0; mt < 2; mt++)
        #pragma unroll
        for (int nt = 0; nt < 4; nt++)
            #pragma unroll
            for (int q = 0; q < 4; q++) acc[mt][nt][q] = 0.0f;

    #pragma unroll
    for (int ks = 0; ks < 8; ks++) {
        const uint32_t uA = (uint32_t)(((2 * ks + akh) ^ sw) << 4);
        const uint32_t uB = (uint32_t)(((2 * ks + bkh) ^ sw) << 4);
        uint32_t aHi[2][4];
        ldmx4(aHi[0], sA0h + uA);
        ldmx4(aHi[1], sA0h + 16 * 256 + uA);
        #pragma unroll
        for (int np = 0; np < 2; np++) {
            uint32_t bh[4];
            ldmx4(bh, sB0h + np * 16 * 256 + uB);
            #pragma unroll
            for (int mt = 0; mt < 2; mt++) {
                mma_f16(acc[mt][2 * np],     aHi[mt], bh[0], bh[1]);
                mma_f16(acc[mt][2 * np + 1], aHi[mt], bh[2], bh[3]);
            }
        }
    }

    __syncthreads();
    float* stg = (float*)sm;   // 128*EPAD*4 = 34816 <= 48KB
    const int g = lane >> 2, tig = lane & 3;
    #pragma unroll
    for (int mt = 0; mt < 2; mt++) {
        const int r0 = wm * 32 + mt * 16 + g;
        #pragma unroll
        for (int nt = 0; nt < 4; nt++) {
            const int col = wn * 32 + nt * 8 + 2 * tig;
            *(float2*)(stg + r0 * EPAD + col)       = make_float2(acc[mt][nt][0], acc[mt][nt][1]);
            *(float2*)(stg + (r0 + 8) * EPAD + col) = make_float2(acc[mt][nt][2], acc[mt][nt][3]);
        }
    }
    __syncthreads();
    #pragma unroll 4
    for (int i = tid; i < 128 * 16; i += 256) {
        const int row = i >> 4, u = i & 15, col = u * 4;
        float4 v = *(const float4*)(stg + row * EPAD + col);
        v.x += sbias[col]; v.y += sbias[col + 1]; v.z += sbias[col + 2]; v.w += sbias[col + 3];
        *(float4*)(out + (long long)(m0 + row) * ldout + n0 + col) = v;
    }
}

// ============================================================================
// Kernel B: MMA RNN scan (round-9 structure, fp16 3-term — recurrence keeps
// full split precision). 64 CTAs x 256 threads; CTA owns 16 batch rows.
// W_hh fragments preloaded into registers; h double-buffered in swizzled
// smem; one __syncthreads per step.
// ============================================================================
#define SXP 260
#define SCAN_OFF_WH  0
#define SCAN_OFF_AT  65536
#define SCAN_OFF_SX  (65536 + 16384)
#define SCAN_SMEM    (SCAN_OFF_SX + 16 * SXP * 4)

__global__ void __launch_bounds__(256, 1) k_rnn_mma(const int* __restrict__ x)
{
    extern __shared__ __align__(16) char sm[];
    char* WHhi = sm + SCAN_OFF_WH;
    char* WHlo = sm + SCAN_OFF_WH + 32768;
    char* AT   = sm + SCAN_OFF_AT;
    int*  sx   = (int*)(sm + SCAN_OFF_SX);

    const int tid = threadIdx.x, w = tid >> 5, lane = tid & 31;
    const int b0 = blockIdx.x * 16;

    load_tile(g_WHhi, WHhi, 128, tid);
    load_tile(g_WHlo, WHlo, 128, tid);
    for (int i = tid; i < 16 * SEQ; i += 256) {
        int row = i >> 8, t = i & 255;
        sx[row * SXP + t] = x[(b0 + row) * SEQ + t];
    }
    for (int i = tid; i < 512; i += 256)
        ((uint4*)AT)[i] = make_uint4(0, 0, 0, 0);
    __syncthreads();

    // preload B fragments (W_hh) — static for all 256 steps
    const int sw = lane & 7;
    const int brow = w * 16 + (lane & 7) + 8 * (lane >> 4);
    const int bkh  = (lane >> 3) & 1;
    const uint32_t sBh = smem_u32(WHhi) + brow * 256;
    const uint32_t sBl = smem_u32(WHlo) + brow * 256;
    uint32_t bfh[8][4], bfl[8][4];
    #pragma unroll
    for (int ks = 0; ks < 8; ks++) {
        const uint32_t uB = (uint32_t)(((2 * ks + bkh) ^ sw) << 4);
        ldmx4(bfh[ks], sBh + uB);
        ldmx4(bfl[ks], sBl + uB);
    }

    const int arow = lane & 15;
    const int akh  = lane >> 4;
    const uint32_t aBase[2][2] = {
        { smem_u32(AT) + arow * 256,        smem_u32(AT) + 4096 + arow * 256 },
        { smem_u32(AT) + 8192 + arow * 256, smem_u32(AT) + 12288 + arow * 256 } };

    const int g = lane >> 2, tig = lane & 3;
    const int cb[2] = { w * 16 + 2 * tig, w * 16 + 8 + 2 * tig };
    uint32_t stoff[2][2];
    #pragma unroll
    for (int rh = 0; rh < 2; rh++) {
        const int row = g + rh * 8;
        #pragma unroll
        for (int nt = 0; nt < 2; nt++)
            stoff[rh][nt] = (uint32_t)(row * 256 + (((2 * w + nt) ^ (row & 7)) << 4) + 4 * tig);
    }

    int cur = 0;
    for (int t = 0; t < SEQ; t++) {
        const int idx0 = sx[g * SXP + t];
        const int idx1 = sx[(g + 8) * SXP + t];
        float2 px[2][2];
        px[0][0] = *(const float2*)(g_P + idx0 * HID + cb[0]);
        px[0][1] = *(const float2*)(g_P + idx0 * HID + cb[1]);
        px[1][0] = *(const float2*)(g_P + idx1 * HID + cb[0]);
        px[1][1] = *(const float2*)(g_P + idx1 * HID + cb[1]);

        float accH[2][4], accM[2][4], accL[2][4];
        #pragma unroll
        for (int nt = 0; nt < 2; nt++)
            #pragma unroll
            for (int q = 0; q < 4; q++) { accH[nt][q] = 0.f; accM[nt][q] = 0.f; accL[nt][q] = 0.f; }

        const uint32_t aH = aBase[cur][0], aL = aBase[cur][1];
        #pragma unroll
        for (int ks = 0; ks < 8; ks++) {
            const uint32_t uA = (uint32_t)(((2 * ks + akh) ^ sw) << 4);
            uint32_t ahi[4], alo[4];
            ldmx4(ahi, aH + uA);
            ldmx4(alo, aL + uA);
            mma_f16(accH[0], ahi, bfh[ks][0], bfh[ks][1]);
            mma_f16(accH[1], ahi, bfh[ks][2], bfh[ks][3]);
            mma_f16(accM[0], ahi, bfl[ks][0], bfl[ks][1]);
            mma_f16(accM[1], ahi, bfl[ks][2], bfl[ks][3]);
            mma_f16(accL[0], alo, bfh[ks][0], bfh[ks][1]);
            mma_f16(accL[1], alo, bfh[ks][2], bfh[ks][3]);
        }

        const int nxt = cur ^ 1;
        char* Dhi = AT + nxt * 8192;
        char* Dlo = AT + nxt * 8192 + 4096;
        #pragma unroll
        for (int rh = 0; rh < 2; rh++) {
            #pragma unroll
            for (int nt = 0; nt < 2; nt++) {
                const int q0 = 2 * rh;
                float v0 = accH[nt][q0]     + accM[nt][q0]     + accL[nt][q0]     + px[rh][nt].x;
                float v1 = accH[nt][q0 + 1] + accM[nt][q0 + 1] + accL[nt][q0 + 1] + px[rh][nt].y;
                float h0 = fast_tanh(v0), h1 = fast_tanh(v1);
                uint32_t plo, phi = pack_hi(h0, h1, plo);
                *(uint32_t*)(Dhi + stoff[rh][nt]) = phi;
                *(uint32_t*)(Dlo + stoff[rh][nt]) = plo;
            }
        }
        cur = nxt;
        __syncthreads();
    }

    char* Fhi = AT + cur * 8192;
    char* Flo = AT + cur * 8192 + 4096;
    for (int i = tid; i < 16 * 64; i += 256) {
        const int row = i >> 6, cp = i & 63;
        const uint32_t off = (uint32_t)(row * 256 + (((cp >> 2) ^ (row & 7)) << 4) + (cp & 3) * 4);
        ((uint32_t*)g_Hhi)[(b0 + row) * 64 + cp] = *(const uint32_t*)(Fhi + off);
        ((uint32_t*)g_Hlo)[(b0 + row) * 64 + cp] = *(const uint32_t*)(Flo + off);
    }
}

// ============================================================================
// launch
// ============================================================================
extern "C" void kernel_launch(void* const* d_in, const int* in_sizes, int n_in,
                              void* d_out, int out_size) {
    const int*   x    = (const int*)d_in[0];     // int32: JAX downcasts int64
    const float* emb  = (const float*)d_in[1];
    const float* W_ih = (const float*)d_in[2];
    const float* W_hh = (const float*)d_in[3];
    const float* b_ih = (const float*)d_in[4];
    const float* b_hh = (const float*)d_in[5];
    const float* W_fc = (const float*)d_in[6];
    const float* b_fc = (const float*)d_in[7];
    float*       out  = (float*)d_out;

    static float* P_p = nullptr;
    static __half *Ehi_p, *Elo_p, *Whi_p, *Wlo_p, *IHhi_p, *IHlo_p;
    static __half *WHhi_p, *WHlo_p, *Hhi_p, *Hlo_p;
    if (!P_p) {
        cudaGetSymbolAddress((void**)&P_p,    g_P);
        cudaGetSymbolAddress((void**)&Ehi_p,  g_Ehi);
        cudaGetSymbolAddress((void**)&Elo_p,  g_Elo);
        cudaGetSymbolAddress((void**)&Whi_p,  g_Whi);
        cudaGetSymbolAddress((void**)&Wlo_p,  g_Wlo);
        cudaGetSymbolAddress((void**)&IHhi_p, g_IHhi);
        cudaGetSymbolAddress((void**)&IHlo_p, g_IHlo);
        cudaGetSymbolAddress((void**)&WHhi_p, g_WHhi);
        cudaGetSymbolAddress((void**)&WHlo_p, g_WHlo);
        cudaGetSymbolAddress((void**)&Hhi_p,  g_Hhi);
        cudaGetSymbolAddress((void**)&Hlo_p,  g_Hlo);
        cudaFuncSetAttribute(k_gemm,    cudaFuncAttributeMaxDynamicSharedMemorySize, GEMM_SMEM);
        cudaFuncSetAttribute(k_gemm1,   cudaFuncAttributeMaxDynamicSharedMemorySize, G1_SMEM);
        cudaFuncSetAttribute(k_rnn_mma, cudaFuncAttributeMaxDynamicSharedMemorySize, SCAN_SMEM);
    }

    // pre-split to hi/lo fp16 (K padded to 128)
    k_cvt<<<VOCAB / 8, 256>>>(emb,  EMBED, Ehi_p,  Elo_p);
    k_cvt<<<HID / 8,   256>>>(W_ih, EMBED, IHhi_p, IHlo_p);
    k_cvt<<<HID / 8,   256>>>(W_hh, HID,   WHhi_p, WHlo_p);
    k_cvt<<<VOCAB / 8, 256>>>(W_fc, HID,   Whi_p,  Wlo_p);

    // P[v][j] = emb[v]·W_ih[j] + (b_ih+b_hh)[j]  (3-term: P near-fp32)
    k_gemm<<<dim3(VOCAB / 128, HID / 64), 256, GEMM_SMEM>>>(
        Ehi_p, Elo_p, IHhi_p, IHlo_p, P_p, HID, b_ih, b_hh);

    // recurrent scan on tensor cores, 3-term fp16 (writes g_Hhi/g_Hlo)
    k_rnn_mma<<<BATCH / 16, 256, SCAN_SMEM>>>(x);

    // head: single-term fp16 (error budget ~2e-4 spent here)
    k_gemm1<<<dim3(BATCH / 128, VOCAB / 64), 256, G1_SMEM>>>(
        Hhi_p, Whi_p, out, VOCAB, b_fc);
}

// round 12
// speedup vs baseline: 1.3085x; 1.0106x over previous
#include <cuda_runtime.h>
#include <cuda_fp16.h>
#include <cstdint>

// Problem constants
#define VOCAB  32000
#define EMBED  100
#define HID    128
#define BATCH  1024
#define SEQ    256

// -------- device scratch (no allocation allowed) --------
__device__ __align__(16) float g_P[VOCAB * HID];        // fused projections (16.4 MB)
__device__ __align__(16) __half g_Ehi[VOCAB * 128];     // emb split (padded K=128)
__device__ __align__(16) __half g_Elo[VOCAB * 128];
__device__ __align__(16) __half g_Whi[VOCAB * 128];     // W_fc split
__device__ __align__(16) __half g_Wlo[VOCAB * 128];
__device__ __align__(16) __half g_IHhi[128 * 128];      // W_ih split
__device__ __align__(16) __half g_IHlo[128 * 128];
__device__ __align__(16) __half g_WHhi[128 * 128];      // W_hh split
__device__ __align__(16) __half g_WHlo[128 * 128];
__device__ __align__(16) __half g_Hhi[BATCH * 128];     // h_last split
__device__ __align__(16) __half g_Hlo[BATCH * 128];

// ============================================================================
// Pre-split conversion: fp32 [rows][Kv] -> hi/lo fp16 [rows][128] (zero-pad).
// ============================================================================
__global__ void __launch_bounds__(256) k_cvt(
    const float* __restrict__ src, int Kv,
    __half* __restrict__ hi, __half* __restrict__ lo)
{
    const int r    = blockIdx.x * 8 + (threadIdx.x >> 5);
    const int lane = threadIdx.x & 31;
    #pragma unroll
    for (int cp = lane; cp < 64; cp += 32) {
        const int c0 = 2 * cp;
        float a = (c0     < Kv) ? src[(long long)r * Kv + c0]     : 0.0f;
        float b = (c0 + 1 < Kv) ? src[(long long)r * Kv + c0 + 1] : 0.0f;
        __half ha = __float2half_rn(a), hb = __float2half_rn(b);
        __half la = __float2half_rn(a - __half2float(ha));
        __half lb = __float2half_rn(b - __half2float(hb));
        ((uint32_t*)hi)[r * 64 + cp] = (uint32_t)*(uint16_t*)&ha | ((uint32_t)*(uint16_t*)&hb << 16);
        ((uint32_t*)lo)[r * 64 + cp] = (uint32_t)*(uint16_t*)&la | ((uint32_t)*(uint16_t*)&lb << 16);
    }
}

// ============================================================================
// mma.sync helpers (fp16 in / fp32 accum)
// ============================================================================
__device__ __forceinline__ uint32_t smem_u32(const void* p) {
    uint32_t a;
    asm("{ .reg .u64 t; cvta.to.shared.u64 t, %1; cvt.u32.u64 %0, t; }" : "=r"(a) : "l"(p));
    return a;
}
__device__ __forceinline__ void ldmx4(uint32_t* r, uint32_t a) {
    asm volatile("ldmatrix.sync.aligned.m8n8.x4.shared.b16 {%0,%1,%2,%3}, [%4];"
                 : "=r"(r[0]), "=r"(r[1]), "=r"(r[2]), "=r"(r[3]) : "r"(a));
}
__device__ __forceinline__ void mma_f16(float* c, const uint32_t* a,
                                        uint32_t b0, uint32_t b1) {
    asm volatile("mma.sync.aligned.m16n8k16.row.col.f32.f16.f16.f32 "
                 "{%0,%1,%2,%3}, {%4,%5,%6,%7}, {%8,%9}, {%0,%1,%2,%3};"
                 : "+f"(c[0]), "+f"(c[1]), "+f"(c[2]), "+f"(c[3])
                 : "r"(a[0]), "r"(a[1]), "r"(a[2]), "r"(a[3]), "r"(b0), "r"(b1));
}
__device__ __forceinline__ uint32_t tswz(int row, int u) {
    return (uint32_t)(row * 256 + ((u ^ (row & 7)) << 4));
}
__device__ __forceinline__ void load_tile(const __half* __restrict__ g,
                                          char* s, int rows, int tid) {
    #pragma unroll 4
    for (int i = tid; i < rows * 16; i += 256) {
        int row = i >> 4, u = i & 15;
        *(uint4*)(s + tswz(row, u)) = *(const uint4*)(g + (long long)row * 128 + u * 8);
    }
}
__device__ __forceinline__ float fast_tanh(float x) {
    float e = __expf(2.0f * x);
    return 1.0f - __fdividef(2.0f, e + 1.0f);
}
__device__ __forceinline__ uint32_t pack_hi(float a, float b, uint32_t& lo_out) {
    __half ha = __float2half_rn(a), hb = __float2half_rn(b);
    __half la = __float2half_rn(a - __half2float(ha));
    __half lb = __float2half_rn(b - __half2float(hb));
    lo_out = (uint32_t)*(uint16_t*)&la | ((uint32_t)*(uint16_t*)&lb << 16);
    return (uint32_t)*(uint16_t*)&ha | ((uint32_t)*(uint16_t*)&hb << 16);
}
#define CP_ASYNC16(dst, src) \
    asm volatile("cp.async.cg.shared.global [%0], [%1], 16;" :: "r"(dst), "l"(src) : "memory")
#define CP_COMMIT() asm volatile("cp.async.commit_group;" ::: "memory")
#define CP_WAIT0()  asm volatile("cp.async.wait_group 0;" ::: "memory")

// ============================================================================
// k_gemm: 3-term split GEMM (P projection). 128M x 64N, K=128, 8 warps, occ 2.
// (unchanged from passing R11)
// ============================================================================
#define A_TILE 32768
#define B_TILE 16384
#define GEMM_SMEM (2 * A_TILE + 2 * B_TILE)   // 98304
#define EPAD 68

__global__ void __launch_bounds__(256, 2) k_gemm(
    const __half* __restrict__ Ahi_g, const __half* __restrict__ Alo_g,
    const __half* __restrict__ Bhi_g, const __half* __restrict__ Blo_g,
    float* __restrict__ out, long long ldout,
    const float* __restrict__ bias1, const float* __restrict__ bias2)
{
    extern __shared__ __align__(16) char sm[];
    __shared__ float sbias[64];
    char* Ahi = sm;
    char* Alo = sm + A_TILE;
    char* Bhi = sm + 2 * A_TILE;
    char* Blo = sm + 2 * A_TILE + B_TILE;

    const int tid = threadIdx.x, w = tid >> 5, lane = tid & 31;
    const int wm = w >> 1, wn = w & 1;
    const int m0 = blockIdx.x * 128, n0 = blockIdx.y * 64;

    load_tile(Ahi_g + (long long)m0 * 128, Ahi, 128, tid);
    load_tile(Alo_g + (long long)m0 * 128, Alo, 128, tid);
    load_tile(Bhi_g + (long long)n0 * 128, Bhi, 64, tid);
    load_tile(Blo_g + (long long)n0 * 128, Blo, 64, tid);
    if (tid < 64) sbias[tid] = bias1[n0 + tid] + (bias2 ? bias2[n0 + tid] : 0.0f);
    __syncthreads();

    const int sw = lane & 7;
    const int arow = wm * 32 + (lane & 15);
    const int akh  = lane >> 4;
    const int brow = wn * 32 + (lane & 7) + 8 * (lane >> 4);
    const int bkh  = (lane >> 3) & 1;

    const uint32_t sA0h = smem_u32(Ahi) + arow * 256;
    const uint32_t sA0l = smem_u32(Alo) + arow * 256;
    const uint32_t sB0h = smem_u32(Bhi) + brow * 256;
    const uint32_t sB0l = smem_u32(Blo) + brow * 256;

    float acc[2][4][4];
    #pragma unroll
    for (int mt = 0; mt < 2; mt++)
        #pragma unroll
        for (int nt = 0; nt < 4; nt++)
            #pragma unroll
            for (int q = 0; q < 4; q++) acc[mt][nt][q] = 0.0f;

    #pragma unroll
    for (int ks = 0; ks < 8; ks++) {
        const uint32_t uA = (uint32_t)(((2 * ks + akh) ^ sw) << 4);
        const uint32_t uB = (uint32_t)(((2 * ks + bkh) ^ sw) << 4);
        uint32_t aHi[2][4], aLo[2][4];
        ldmx4(aHi[0], sA0h + uA);
        ldmx4(aHi[1], sA0h + 16 * 256 + uA);
        ldmx4(aLo[0], sA0l + uA);
        ldmx4(aLo[1], sA0l + 16 * 256 + uA);
        #pragma unroll
        for (int np = 0; np < 2; np++) {
            uint32_t bh[4], bl[4];
            ldmx4(bh, sB0h + np * 16 * 256 + uB);
            ldmx4(bl, sB0l + np * 16 * 256 + uB);
            #pragma unroll
            for (int mt = 0; mt < 2; mt++) {
                mma_f16(acc[mt][2 * np],     aHi[mt], bh[0], bh[1]);
                mma_f16(acc[mt][2 * np + 1], aHi[mt], bh[2], bh[3]);
                mma_f16(acc[mt][2 * np],     aLo[mt], bh[0], bh[1]);
                mma_f16(acc[mt][2 * np + 1], aLo[mt], bh[2], bh[3]);
                mma_f16(acc[mt][2 * np],     aHi[mt], bl[0], bl[1]);
                mma_f16(acc[mt][2 * np + 1], aHi[mt], bl[2], bl[3]);
            }
        }
    }

    __syncthreads();
    float* stg = (float*)sm;
    const int g = lane >> 2, tig = lane & 3;
    #pragma unroll
    for (int mt = 0; mt < 2; mt++) {
        const int r0 = wm * 32 + mt * 16 + g;
        #pragma unroll
        for (int nt = 0; nt < 4; nt++) {
            const int col = wn * 32 + nt * 8 + 2 * tig;
            *(float2*)(stg + r0 * EPAD + col)       = make_float2(acc[mt][nt][0], acc[mt][nt][1]);
            *(float2*)(stg + (r0 + 8) * EPAD + col) = make_float2(acc[mt][nt][2], acc[mt][nt][3]);
        }
    }
    __syncthreads();
    #pragma unroll 4
    for (int i = tid; i < 128 * 16; i += 256) {
        const int row = i >> 4, u = i & 15, col = u * 4;
        float4 v = *(const float4*)(stg + row * EPAD + col);
        v.x += sbias[col]; v.y += sbias[col + 1]; v.z += sbias[col + 2]; v.w += sbias[col + 3];
        *(float4*)(out + (long long)(m0 + row) * ldout + n0 + col) = v;
    }
}

// ============================================================================
// k_head: persistent-strip single-term fp16 head GEMM.
// Grid (8, 50): CTA owns batch tile m0 (A loaded ONCE) and a strip of 10
// W_fc N-tiles (64 cols each). B double-buffered via cp.async: load(ti+1)
// issued before compute(ti), wait_group+bar after. Direct fragment epilogue.
// smem = A 32KB + 2xB 16KB + bias 2.5KB = 68KB.
// ============================================================================
#define NT_STRIP 10
#define HD_SMEM (A_TILE + 2 * B_TILE + NT_STRIP * 64 * 4)

__global__ void __launch_bounds__(256, 2) k_head(
    const __half* __restrict__ Ahi_g, const __half* __restrict__ Bhi_g,
    float* __restrict__ out, const float* __restrict__ bias)
{
    extern __shared__ __align__(16) char sm[];
    char* A  = sm;
    char* Bb = sm + A_TILE;                       // two 16KB buffers
    float* sbias = (float*)(sm + A_TILE + 2 * B_TILE);

    const int tid = threadIdx.x, w = tid >> 5, lane = tid & 31;
    const int wm = w >> 1, wn = w & 1;
    const int m0 = blockIdx.x * 128;
    const int nbase = blockIdx.y * (NT_STRIP * 64);

    // prologue: A tile + B0 via cp.async, bias via LDG
    {
        const __half* Ag = Ahi_g + (long long)m0 * 128;
        #pragma unroll 2
        for (int i = tid; i < 128 * 16; i += 256) {
            int row = i >> 4, u = i & 15;
            CP_ASYNC16(smem_u32(A + tswz(row, u)), Ag + (long long)row * 128 + u * 8);
        }
        const __half* Bg = Bhi_g + (long long)nbase * 128;
        for (int i = tid; i < 64 * 16; i += 256) {
            int row = i >> 4, u = i & 15;
            CP_ASYNC16(smem_u32(Bb + tswz(row, u)), Bg + (long long)row * 128 + u * 8);
        }
        CP_COMMIT();
        for (int i = tid; i < NT_STRIP * 64; i += 256) sbias[i] = bias[nbase + i];
        CP_WAIT0();
        __syncthreads();
    }

    const int sw = lane & 7;
    const int arow = wm * 32 + (lane & 15);
    const int akh  = lane >> 4;
    const int brow = wn * 32 + (lane & 7) + 8 * (lane >> 4);
    const int bkh  = (lane >> 3) & 1;
    const uint32_t sA0 = smem_u32(A) + arow * 256;
    const int g = lane >> 2, tig = lane & 3;

    int buf = 0;
    for (int ti = 0; ti < NT_STRIP; ti++) {
        // prefetch next B tile into the other buffer
        if (ti < NT_STRIP - 1) {
            const __half* Bg = Bhi_g + (long long)(nbase + (ti + 1) * 64) * 128;
            char* Bn = Bb + (buf ^ 1) * B_TILE;
            for (int i = tid; i < 64 * 16; i += 256) {
                int row = i >> 4, u = i & 15;
                CP_ASYNC16(smem_u32(Bn + tswz(row, u)), Bg + (long long)row * 128 + u * 8);
            }
            CP_COMMIT();
        }

        const uint32_t sB0 = smem_u32(Bb + buf * B_TILE) + brow * 256;
        float acc[2][4][4];
        #pragma unroll
        for (int mt = 0; mt < 2; mt++)
            #pragma unroll
            for (int nt = 0; nt < 4; nt++)
                #pragma unroll
                for (int q = 0; q < 4; q++) acc[mt][nt][q] = 0.0f;

        #pragma unroll
        for (int ks = 0; ks < 8; ks++) {
            const uint32_t uA = (uint32_t)(((2 * ks + akh) ^ sw) << 4);
            const uint32_t uB = (uint32_t)(((2 * ks + bkh) ^ sw) << 4);
            uint32_t aHi[2][4];
            ldmx4(aHi[0], sA0 + uA);
            ldmx4(aHi[1], sA0 + 16 * 256 + uA);
            #pragma unroll
            for (int np = 0; np < 2; np++) {
                uint32_t bh[4];
                ldmx4(bh, sB0 + np * 16 * 256 + uB);
                #pragma unroll
                for (int mt = 0; mt < 2; mt++) {
                    mma_f16(acc[mt][2 * np],     aHi[mt], bh[0], bh[1]);
                    mma_f16(acc[mt][2 * np + 1], aHi[mt], bh[2], bh[3]);
                }
            }
        }

        // direct epilogue (frag layout float2 stores)
        const int n0 = nbase + ti * 64;
        #pragma unroll
        for (int mt = 0; mt < 2; mt++) {
            const long long r0 = (long long)(m0 + wm * 32 + mt * 16 + g) * VOCAB + n0;
            const long long r1 = r0 + 8LL * VOCAB;
            #pragma unroll
            for (int nt = 0; nt < 4; nt++) {
                const int col = wn * 32 + nt * 8 + 2 * tig;
                const float bx = sbias[ti * 64 + col], by = sbias[ti * 64 + col + 1];
                *(float2*)(out + r0 + col) = make_float2(acc[mt][nt][0] + bx, acc[mt][nt][1] + by);
                *(float2*)(out + r1 + col) = make_float2(acc[mt][nt][2] + bx, acc[mt][nt][3] + by);
            }
        }

        if (ti < NT_STRIP - 1) {
            CP_WAIT0();
            __syncthreads();
            buf ^= 1;
        }
    }
}

// ============================================================================
// Kernel B: MMA RNN scan, fp16 3-term (unchanged from passing R11).
// ============================================================================
#define SXP 260
#define SCAN_OFF_WH  0
#define SCAN_OFF_AT  65536
#define SCAN_OFF_SX  (65536 + 16384)
#define SCAN_SMEM    (SCAN_OFF_SX + 16 * SXP * 4)

__global__ void __launch_bounds__(256, 1) k_rnn_mma(const int* __restrict__ x)
{
    extern __shared__ __align__(16) char sm[];
    char* WHhi = sm + SCAN_OFF_WH;
    char* WHlo = sm + SCAN_OFF_WH + 32768;
    char* AT   = sm + SCAN_OFF_AT;
    int*  sx   = (int*)(sm + SCAN_OFF_SX);

    const int tid = threadIdx.x, w = tid >> 5, lane = tid & 31;
    const int b0 = blockIdx.x * 16;

    load_tile(g_WHhi, WHhi, 128, tid);
    load_tile(g_WHlo, WHlo, 128, tid);
    for (int i = tid; i < 16 * SEQ; i += 256) {
        int row = i >> 8, t = i & 255;
        sx[row * SXP + t] = x[(b0 + row) * SEQ + t];
    }
    for (int i = tid; i < 512; i += 256)
        ((uint4*)AT)[i] = make_uint4(0, 0, 0, 0);
    __syncthreads();

    const int sw = lane & 7;
    const int brow = w * 16 + (lane & 7) + 8 * (lane >> 4);
    const int bkh  = (lane >> 3) & 1;
    const uint32_t sBh = smem_u32(WHhi) + brow * 256;
    const uint32_t sBl = smem_u32(WHlo) + brow * 256;
    uint32_t bfh[8][4], bfl[8][4];
    #pragma unroll
    for (int ks = 0; ks < 8; ks++) {
        const uint32_t uB = (uint32_t)(((2 * ks + bkh) ^ sw) << 4);
        ldmx4(bfh[ks], sBh + uB);
        ldmx4(bfl[ks], sBl + uB);
    }

    const int arow = lane & 15;
    const int akh  = lane >> 4;
    const uint32_t aBase[2][2] = {
        { smem_u32(AT) + arow * 256,        smem_u32(AT) + 4096 + arow * 256 },
        { smem_u32(AT) + 8192 + arow * 256, smem_u32(AT) + 12288 + arow * 256 } };

    const int g = lane >> 2, tig = lane & 3;
    const int cb[2] = { w * 16 + 2 * tig, w * 16 + 8 + 2 * tig };
    uint32_t stoff[2][2];
    #pragma unroll
    for (int rh = 0; rh < 2; rh++) {
        const int row = g + rh * 8;
        #pragma unroll
        for (int nt = 0; nt < 2; nt++)
            stoff[rh][nt] = (uint32_t)(row * 256 + (((2 * w + nt) ^ (row & 7)) << 4) + 4 * tig);
    }

    int cur = 0;
    for (int t = 0; t < SEQ; t++) {
        const int idx0 = sx[g * SXP + t];
        const int idx1 = sx[(g + 8) * SXP + t];
        float2 px[2][2];
        px[0][0] = *(const float2*)(g_P + idx0 * HID + cb[0]);
        px[0][1] = *(const float2*)(g_P + idx0 * HID + cb[1]);
        px[1][0] = *(const float2*)(g_P + idx1 * HID + cb[0]);
        px[1][1] = *(const float2*)(g_P + idx1 * HID + cb[1]);

        float accH[2][4], accM[2][4], accL[2][4];
        #pragma unroll
        for (int nt = 0; nt < 2; nt++)
            #pragma unroll
            for (int q = 0; q < 4; q++) { accH[nt][q] = 0.f; accM[nt][q] = 0.f; accL[nt][q] = 0.f; }

        const uint32_t aH = aBase[cur][0], aL = aBase[cur][1];
        #pragma unroll
        for (int ks = 0; ks < 8; ks++) {
            const uint32_t uA = (uint32_t)(((2 * ks + akh) ^ sw) << 4);
            uint32_t ahi[4], alo[4];
            ldmx4(ahi, aH + uA);
            ldmx4(alo, aL + uA);
            mma_f16(accH[0], ahi, bfh[ks][0], bfh[ks][1]);
            mma_f16(accH[1], ahi, bfh[ks][2], bfh[ks][3]);
            mma_f16(accM[0], ahi, bfl[ks][0], bfl[ks][1]);
            mma_f16(accM[1], ahi, bfl[ks][2], bfl[ks][3]);
            mma_f16(accL[0], alo, bfh[ks][0], bfh[ks][1]);
            mma_f16(accL[1], alo, bfh[ks][2], bfh[ks][3]);
        }

        const int nxt = cur ^ 1;
        char* Dhi = AT + nxt * 8192;
        char* Dlo = AT + nxt * 8192 + 4096;
        #pragma unroll
        for (int rh = 0; rh < 2; rh++) {
            #pragma unroll
            for (int nt = 0; nt < 2; nt++) {
                const int q0 = 2 * rh;
                float v0 = accH[nt][q0]     + accM[nt][q0]     + accL[nt][q0]     + px[rh][nt].x;
                float v1 = accH[nt][q0 + 1] + accM[nt][q0 + 1] + accL[nt][q0 + 1] + px[rh][nt].y;
                float h0 = fast_tanh(v0), h1 = fast_tanh(v1);
                uint32_t plo, phi = pack_hi(h0, h1, plo);
                *(uint32_t*)(Dhi + stoff[rh][nt]) = phi;
                *(uint32_t*)(Dlo + stoff[rh][nt]) = plo;
            }
        }
        cur = nxt;
        __syncthreads();
    }

    char* Fhi = AT + cur * 8192;
    char* Flo = AT + cur * 8192 + 4096;
    for (int i = tid; i < 16 * 64; i += 256) {
        const int row = i >> 6, cp = i & 63;
        const uint32_t off = (uint32_t)(row * 256 + (((cp >> 2) ^ (row & 7)) << 4) + (cp & 3) * 4);
        ((uint32_t*)g_Hhi)[(b0 + row) * 64 + cp] = *(const uint32_t*)(Fhi + off);
        ((uint32_t*)g_Hlo)[(b0 + row) * 64 + cp] = *(const uint32_t*)(Flo + off);
    }
}

// ============================================================================
// launch
// ============================================================================
extern "C" void kernel_launch(void* const* d_in, const int* in_sizes, int n_in,
                              void* d_out, int out_size) {
    const int*   x    = (const int*)d_in[0];     // int32: JAX downcasts int64
    const float* emb  = (const float*)d_in[1];
    const float* W_ih = (const float*)d_in[2];
    const float* W_hh = (const float*)d_in[3];
    const float* b_ih = (const float*)d_in[4];
    const float* b_hh = (const float*)d_in[5];
    const float* W_fc = (const float*)d_in[6];
    const float* b_fc = (const float*)d_in[7];
    float*       out  = (float*)d_out;

    static float* P_p = nullptr;
    static __half *Ehi_p, *Elo_p, *Whi_p, *Wlo_p, *IHhi_p, *IHlo_p;
    static __half *WHhi_p, *WHlo_p, *Hhi_p, *Hlo_p;
    if (!P_p) {
        cudaGetSymbolAddress((void**)&P_p,    g_P);
        cudaGetSymbolAddress((void**)&Ehi_p,  g_Ehi);
        cudaGetSymbolAddress((void**)&Elo_p,  g_Elo);
        cudaGetSymbolAddress((void**)&Whi_p,  g_Whi);
        cudaGetSymbolAddress((void**)&Wlo_p,  g_Wlo);
        cudaGetSymbolAddress((void**)&IHhi_p, g_IHhi);
        cudaGetSymbolAddress((void**)&IHlo_p, g_IHlo);
        cudaGetSymbolAddress((void**)&WHhi_p, g_WHhi);
        cudaGetSymbolAddress((void**)&WHlo_p, g_WHlo);
        cudaGetSymbolAddress((void**)&Hhi_p,  g_Hhi);
        cudaGetSymbolAddress((void**)&Hlo_p,  g_Hlo);
        cudaFuncSetAttribute(k_gemm,    cudaFuncAttributeMaxDynamicSharedMemorySize, GEMM_SMEM);
        cudaFuncSetAttribute(k_head,    cudaFuncAttributeMaxDynamicSharedMemorySize, HD_SMEM);
        cudaFuncSetAttribute(k_rnn_mma, cudaFuncAttributeMaxDynamicSharedMemorySize, SCAN_SMEM);
    }

    // pre-split to hi/lo fp16 (K padded to 128)
    k_cvt<<<VOCAB / 8, 256>>>(emb,  EMBED, Ehi_p,  Elo_p);
    k_cvt<<<HID / 8,   256>>>(W_ih, EMBED, IHhi_p, IHlo_p);
    k_cvt<<<HID / 8,   256>>>(W_hh, HID,   WHhi_p, WHlo_p);
    k_cvt<<<VOCAB / 8, 256>>>(W_fc, HID,   Whi_p,  Wlo_p);

    // P[v][j] = emb[v]·W_ih[j] + (b_ih+b_hh)[j]  (3-term: P near-fp32)
    k_gemm<<<dim3(VOCAB / 128, HID / 64), 256, GEMM_SMEM>>>(
        Ehi_p, Elo_p, IHhi_p, IHlo_p, P_p, HID, b_ih, b_hh);

    // recurrent scan on tensor cores, 3-term fp16 (writes g_Hhi/g_Hlo)
    k_rnn_mma<<<BATCH / 16, 256, SCAN_SMEM>>>(x);

    // head: persistent-strip single-term fp16
    k_head<<<dim3(BATCH / 128, VOCAB / (NT_STRIP * 64)), 256, HD_SMEM>>>(
        Hhi_p, Whi_p, out, b_fc);
}

// round 13
// speedup vs baseline: 1.5871x; 1.2129x over previous
#include <cuda_runtime.h>
#include <cuda_fp16.h>
#include <cstdint>

// Problem constants
#define VOCAB  32000
#define EMBED  100
#define HID    128
#define BATCH  1024
#define SEQ    256

// -------- device scratch (no allocation allowed) --------
__device__ __align__(16) float g_P[VOCAB * HID];        // fused projections (16.4 MB)
__device__ __align__(16) __half g_Ehi[VOCAB * 128];     // emb split (padded K=128)
__device__ __align__(16) __half g_Elo[VOCAB * 128];
__device__ __align__(16) __half g_Whi[VOCAB * 128];     // W_fc hi (head is single-term)
__device__ __align__(16) __half g_IHhi[128 * 128];      // W_ih split
__device__ __align__(16) __half g_IHlo[128 * 128];
__device__ __align__(16) __half g_WHhi[128 * 128];      // W_hh split
__device__ __align__(16) __half g_WHlo[128 * 128];
__device__ __align__(16) __half g_Hhi[BATCH * 128];     // h_last split
__device__ __align__(16) __half g_Hlo[BATCH * 128];

// ============================================================================
// Pre-split conversion: fp32 [rows][Kv] -> hi/lo fp16 [rows][128] (zero-pad).
// ============================================================================
__global__ void __launch_bounds__(256) k_cvt(
    const float* __restrict__ src, int Kv,
    __half* __restrict__ hi, __half* __restrict__ lo)
{
    const int r    = blockIdx.x * 8 + (threadIdx.x >> 5);
    const int lane = threadIdx.x & 31;
    #pragma unroll
    for (int cp = lane; cp < 64; cp += 32) {
        const int c0 = 2 * cp;
        float a = (c0     < Kv) ? src[(long long)r * Kv + c0]     : 0.0f;
        float b = (c0 + 1 < Kv) ? src[(long long)r * Kv + c0 + 1] : 0.0f;
        __half ha = __float2half_rn(a), hb = __float2half_rn(b);
        __half la = __float2half_rn(a - __half2float(ha));
        __half lb = __float2half_rn(b - __half2float(hb));
        ((uint32_t*)hi)[r * 64 + cp] = (uint32_t)*(uint16_t*)&ha | ((uint32_t)*(uint16_t*)&hb << 16);
        ((uint32_t*)lo)[r * 64 + cp] = (uint32_t)*(uint16_t*)&la | ((uint32_t)*(uint16_t*)&lb << 16);
    }
}
// hi-only variant (head never reads W_fc lo)
__global__ void __launch_bounds__(256) k_cvt_hi(
    const float* __restrict__ src, int Kv, __half* __restrict__ hi)
{
    const int r    = blockIdx.x * 8 + (threadIdx.x >> 5);
    const int lane = threadIdx.x & 31;
    #pragma unroll
    for (int cp = lane; cp < 64; cp += 32) {
        const int c0 = 2 * cp;
        float a = (c0     < Kv) ? src[(long long)r * Kv + c0]     : 0.0f;
        float b = (c0 + 1 < Kv) ? src[(long long)r * Kv + c0 + 1] : 0.0f;
        __half ha = __float2half_rn(a), hb = __float2half_rn(b);
        ((uint32_t*)hi)[r * 64 + cp] = (uint32_t)*(uint16_t*)&ha | ((uint32_t)*(uint16_t*)&hb << 16);
    }
}

// ============================================================================
// mma.sync helpers (fp16 in / fp32 accum)
// ============================================================================
__device__ __forceinline__ uint32_t smem_u32(const void* p) {
    uint32_t a;
    asm("{ .reg .u64 t; cvta.to.shared.u64 t, %1; cvt.u32.u64 %0, t; }" : "=r"(a) : "l"(p));
    return a;
}
__device__ __forceinline__ void ldmx4(uint32_t* r, uint32_t a) {
    asm volatile("ldmatrix.sync.aligned.m8n8.x4.shared.b16 {%0,%1,%2,%3}, [%4];"
                 : "=r"(r[0]), "=r"(r[1]), "=r"(r[2]), "=r"(r[3]) : "r"(a));
}
__device__ __forceinline__ void ldmx2(uint32_t* r, uint32_t a) {
    asm volatile("ldmatrix.sync.aligned.m8n8.x2.shared.b16 {%0,%1}, [%2];"
                 : "=r"(r[0]), "=r"(r[1]) : "r"(a));
}
__device__ __forceinline__ void mma_f16(float* c, const uint32_t* a,
                                        uint32_t b0, uint32_t b1) {
    asm volatile("mma.sync.aligned.m16n8k16.row.col.f32.f16.f16.f32 "
                 "{%0,%1,%2,%3}, {%4,%5,%6,%7}, {%8,%9}, {%0,%1,%2,%3};"
                 : "+f"(c[0]), "+f"(c[1]), "+f"(c[2]), "+f"(c[3])
                 : "r"(a[0]), "r"(a[1]), "r"(a[2]), "r"(a[3]), "r"(b0), "r"(b1));
}
__device__ __forceinline__ uint32_t tswz(int row, int u) {
    return (uint32_t)(row * 256 + ((u ^ (row & 7)) << 4));
}
__device__ __forceinline__ void load_tile(const __half* __restrict__ g,
                                          char* s, int rows, int tid) {
    #pragma unroll 4
    for (int i = tid; i < rows * 16; i += 256) {
        int row = i >> 4, u = i & 15;
        *(uint4*)(s + tswz(row, u)) = *(const uint4*)(g + (long long)row * 128 + u * 8);
    }
}
__device__ __forceinline__ float fast_tanh(float x) {
    float e = __expf(2.0f * x);
    return 1.0f - __fdividef(2.0f, e + 1.0f);
}
__device__ __forceinline__ uint32_t pack_hi(float a, float b, uint32_t& lo_out) {
    __half ha = __float2half_rn(a), hb = __float2half_rn(b);
    __half la = __float2half_rn(a - __half2float(ha));
    __half lb = __float2half_rn(b - __half2float(hb));
    lo_out = (uint32_t)*(uint16_t*)&la | ((uint32_t)*(uint16_t*)&lb << 16);
    return (uint32_t)*(uint16_t*)&ha | ((uint32_t)*(uint16_t*)&hb << 16);
}
__device__ __forceinline__ uint32_t mapa_peer(uint32_t addr, uint32_t rank) {
    uint32_t r;
    asm("mapa.shared::cluster.u32 %0, %1, %2;" : "=r"(r) : "r"(addr), "r"(rank));
    return r;
}
__device__ __forceinline__ uint32_t my_cluster_rank() {
    uint32_t r;
    asm("mov.u32 %0, %%cluster_ctarank;" : "=r"(r));
    return r;
}
#define CLUSTER_SYNC() do { \
    asm volatile("barrier.cluster.arrive.aligned;" ::: "memory"); \
    asm volatile("barrier.cluster.wait.aligned;" ::: "memory"); } while (0)
#define MBAR_INIT(a, c) \
    asm volatile("mbarrier.init.shared.b64 [%0], %1;" :: "r"(a), "r"(c) : "memory")
#define MBAR_EXPECT_TX(a, bytes) \
    asm volatile("mbarrier.arrive.expect_tx.shared.b64 _, [%0], %1;" :: "r"(a), "r"(bytes) : "memory")
// remote store that credits tx bytes to the destination CTA's mbarrier
#define ST_ASYNC_U32(raddr, val, rmbar) \
    asm volatile("st.async.weak.shared::cluster.mbarrier::complete_tx::bytes.b32 [%0], %1, [%2];" \
                 :: "r"(raddr), "r"(val), "r"(rmbar) : "memory")
__device__ __forceinline__ void mbar_wait_acq(uint32_t mbar, uint32_t parity) {
    uint32_t done;
    asm volatile("{\n\t.reg .pred p;\n\t"
                 "mbarrier.try_wait.parity.acquire.cluster.shared::cta.b64 p, [%1], %2;\n\t"
                 "selp.b32 %0, 1, 0, p;\n\t}" : "=r"(done) : "r"(mbar), "r"(parity) : "memory");
    if (!done) {
        asm volatile("{\n\t.reg .pred P1;\n\tWL%=:\n\t"
                     "mbarrier.try_wait.parity.acquire.cluster.shared::cta.b64 P1, [%0], %1;\n\t"
                     "@P1 bra.uni WD%=;\n\tbra.uni WL%=;\n\tWD%=:\n\t}"
                     :: "r"(mbar), "r"(parity) : "memory");
    }
}
#define CP_ASYNC16(dst, src) \
    asm volatile("cp.async.cg.shared.global [%0], [%1], 16;" :: "r"(dst), "l"(src) : "memory")
#define CP_COMMIT() asm volatile("cp.async.commit_group;" ::: "memory")
#define CP_WAIT0()  asm volatile("cp.async.wait_group 0;" ::: "memory")

// ============================================================================
// k_gemm: 3-term split GEMM (P projection). Unchanged from passing R11/12.
// ============================================================================
#define A_TILE 32768
#define B_TILE 16384
#define GEMM_SMEM (2 * A_TILE + 2 * B_TILE)   // 98304
#define EPAD 68

__global__ void __launch_bounds__(256, 2) k_gemm(
    const __half* __restrict__ Ahi_g, const __half* __restrict__ Alo_g,
    const __half* __restrict__ Bhi_g, const __half* __restrict__ Blo_g,
    float* __restrict__ out, long long ldout,
    const float* __restrict__ bias1, const float* __restrict__ bias2)
{
    extern __shared__ __align__(16) char sm[];
    __shared__ float sbias[64];
    char* Ahi = sm;
    char* Alo = sm + A_TILE;
    char* Bhi = sm + 2 * A_TILE;
    char* Blo = sm + 2 * A_TILE + B_TILE;

    const int tid = threadIdx.x, w = tid >> 5, lane = tid & 31;
    const int wm = w >> 1, wn = w & 1;
    const int m0 = blockIdx.x * 128, n0 = blockIdx.y * 64;

    load_tile(Ahi_g + (long long)m0 * 128, Ahi, 128, tid);
    load_tile(Alo_g + (long long)m0 * 128, Alo, 128, tid);
    load_tile(Bhi_g + (long long)n0 * 128, Bhi, 64, tid);
    load_tile(Blo_g + (long long)n0 * 128, Blo, 64, tid);
    if (tid < 64) sbias[tid] = bias1[n0 + tid] + (bias2 ? bias2[n0 + tid] : 0.0f);
    __syncthreads();

    const int sw = lane & 7;
    const int arow = wm * 32 + (lane & 15);
    const int akh  = lane >> 4;
    const int brow = wn * 32 + (lane & 7) + 8 * (lane >> 4);
    const int bkh  = (lane >> 3) & 1;

    const uint32_t sA0h = smem_u32(Ahi) + arow * 256;
    const uint32_t sA0l = smem_u32(Alo) + arow * 256;
    const uint32_t sB0h = smem_u32(Bhi) + brow * 256;
    const uint32_t sB0l = smem_u32(Blo) + brow * 256;

    float acc[2][4][4];
    #pragma unroll
    for (int mt = 0; mt < 2; mt++)
        #pragma unroll
        for (int nt = 0; nt < 4; nt++)
            #pragma unroll
            for (int q = 0; q < 4; q++) acc[mt][nt][q] = 0.0f;

    #pragma unroll
    for (int ks = 0; ks < 8; ks++) {
        const uint32_t uA = (uint32_t)(((2 * ks + akh) ^ sw) << 4);
        const uint32_t uB = (uint32_t)(((2 * ks + bkh) ^ sw) << 4);
        uint32_t aHi[2][4], aLo[2][4];
        ldmx4(aHi[0], sA0h + uA);
        ldmx4(aHi[1], sA0h + 16 * 256 + uA);
        ldmx4(aLo[0], sA0l + uA);
        ldmx4(aLo[1], sA0l + 16 * 256 + uA);
        #pragma unroll
        for (int np = 0; np < 2; np++) {
            uint32_t bh[4], bl[4];
            ldmx4(bh, sB0h + np * 16 * 256 + uB);
            ldmx4(bl, sB0l + np * 16 * 256 + uB);
            #pragma unroll
            for (int mt = 0; mt < 2; mt++) {
                mma_f16(acc[mt][2 * np],     aHi[mt], bh[0], bh[1]);
                mma_f16(acc[mt][2 * np + 1], aHi[mt], bh[2], bh[3]);
                mma_f16(acc[mt][2 * np],     aLo[mt], bh[0], bh[1]);
                mma_f16(acc[mt][2 * np + 1], aLo[mt], bh[2], bh[3]);
                mma_f16(acc[mt][2 * np],     aHi[mt], bl[0], bl[1]);
                mma_f16(acc[mt][2 * np + 1], aHi[mt], bl[2], bl[3]);
            }
        }
    }

    __syncthreads();
    float* stg = (float*)sm;
    const int g = lane >> 2, tig = lane & 3;
    #pragma unroll
    for (int mt = 0; mt < 2; mt++) {
        const int r0 = wm * 32 + mt * 16 + g;
        #pragma unroll
        for (int nt = 0; nt < 4; nt++) {
            const int col = wn * 32 + nt * 8 + 2 * tig;
            *(float2*)(stg + r0 * EPAD + col)       = make_float2(acc[mt][nt][0], acc[mt][nt][1]);
            *(float2*)(stg + (r0 + 8) * EPAD + col) = make_float2(acc[mt][nt][2], acc[mt][nt][3]);
        }
    }
    __syncthreads();
    #pragma unroll 4
    for (int i = tid; i < 128 * 16; i += 256) {
        const int row = i >> 4, u = i & 15, col = u * 4;
        float4 v = *(const float4*)(stg + row * EPAD + col);
        v.x += sbias[col]; v.y += sbias[col + 1]; v.z += sbias[col + 2]; v.w += sbias[col + 3];
        *(float4*)(out + (long long)(m0 + row) * ldout + n0 + col) = v;
    }
}

// ============================================================================
// k_head: persistent-strip single-term fp16 head GEMM (unchanged from R12).
// ============================================================================
#define NT_STRIP 10
#define HD_SMEM (A_TILE + 2 * B_TILE + NT_STRIP * 64 * 4)

__global__ void __launch_bounds__(256, 2) k_head(
    const __half* __restrict__ Ahi_g, const __half* __restrict__ Bhi_g,
    float* __restrict__ out, const float* __restrict__ bias)
{
    extern __shared__ __align__(16) char sm[];
    char* A  = sm;
    char* Bb = sm + A_TILE;
    float* sbias = (float*)(sm + A_TILE + 2 * B_TILE);

    const int tid = threadIdx.x, w = tid >> 5, lane = tid & 31;
    const int wm = w >> 1, wn = w & 1;
    const int m0 = blockIdx.x * 128;
    const int nbase = blockIdx.y * (NT_STRIP * 64);

    {
        const __half* Ag = Ahi_g + (long long)m0 * 128;
        #pragma unroll 2
        for (int i = tid; i < 128 * 16; i += 256) {
            int row = i >> 4, u = i & 15;
            CP_ASYNC16(smem_u32(A + tswz(row, u)), Ag + (long long)row * 128 + u * 8);
        }
        const __half* Bg = Bhi_g + (long long)nbase * 128;
        for (int i = tid; i < 64 * 16; i += 256) {
            int row = i >> 4, u = i & 15;
            CP_ASYNC16(smem_u32(Bb + tswz(row, u)), Bg + (long long)row * 128 + u * 8);
        }
        CP_COMMIT();
        for (int i = tid; i < NT_STRIP * 64; i += 256) sbias[i] = bias[nbase + i];
        CP_WAIT0();
        __syncthreads();
    }

    const int sw = lane & 7;
    const int arow = wm * 32 + (lane & 15);
    const int akh  = lane >> 4;
    const int brow = wn * 32 + (lane & 7) + 8 * (lane >> 4);
    const int bkh  = (lane >> 3) & 1;
    const uint32_t sA0 = smem_u32(A) + arow * 256;
    const int g = lane >> 2, tig = lane & 3;

    int buf = 0;
    for (int ti = 0; ti < NT_STRIP; ti++) {
        if (ti < NT_STRIP - 1) {
            const __half* Bg = Bhi_g + (long long)(nbase + (ti + 1) * 64) * 128;
            char* Bn = Bb + (buf ^ 1) * B_TILE;
            for (int i = tid; i < 64 * 16; i += 256) {
                int row = i >> 4, u = i & 15;
                CP_ASYNC16(smem_u32(Bn + tswz(row, u)), Bg + (long long)row * 128 + u * 8);
            }
            CP_COMMIT();
        }

        const uint32_t sB0 = smem_u32(Bb + buf * B_TILE) + brow * 256;
        float acc[2][4][4];
        #pragma unroll
        for (int mt = 0; mt < 2; mt++)
            #pragma unroll
            for (int nt = 0; nt < 4; nt++)
                #pragma unroll
                for (int q = 0; q < 4; q++) acc[mt][nt][q] = 0.0f;

        #pragma unroll
        for (int ks = 0; ks < 8; ks++) {
            const uint32_t uA = (uint32_t)(((2 * ks + akh) ^ sw) << 4);
            const uint32_t uB = (uint32_t)(((2 * ks + bkh) ^ sw) << 4);
            uint32_t aHi[2][4];
            ldmx4(aHi[0], sA0 + uA);
            ldmx4(aHi[1], sA0 + 16 * 256 + uA);
            #pragma unroll
            for (int np = 0; np < 2; np++) {
                uint32_t bh[4];
                ldmx4(bh, sB0 + np * 16 * 256 + uB);
                #pragma unroll
                for (int mt = 0; mt < 2; mt++) {
                    mma_f16(acc[mt][2 * np],     aHi[mt], bh[0], bh[1]);
                    mma_f16(acc[mt][2 * np + 1], aHi[mt], bh[2], bh[3]);
                }
            }
        }

        const int n0 = nbase + ti * 64;
        #pragma unroll
        for (int mt = 0; mt < 2; mt++) {
            const long long r0 = (long long)(m0 + wm * 32 + mt * 16 + g) * VOCAB + n0;
            const long long r1 = r0 + 8LL * VOCAB;
            #pragma unroll
            for (int nt = 0; nt < 4; nt++) {
                const int col = wn * 32 + nt * 8 + 2 * tig;
                const float bx = sbias[ti * 64 + col], by = sbias[ti * 64 + col + 1];
                *(float2*)(out + r0 + col) = make_float2(acc[mt][nt][0] + bx, acc[mt][nt][1] + by);
                *(float2*)(out + r1 + col) = make_float2(acc[mt][nt][2] + bx, acc[mt][nt][3] + by);
            }
        }

        if (ti < NT_STRIP - 1) {
            CP_WAIT0();
            __syncthreads();
            buf ^= 1;
        }
    }
}

// ============================================================================
// Kernel B: cluster-of-2 MMA RNN scan with st.async tx-count sync.
// 128 CTAs (64 clusters) x 256 threads. Cluster owns 16 batch rows; rank r
// computes cols [64r, 64r+64): 24 HMMA/warp/step (768 cyc/SMSP vs 1536).
// h exchange: each thread's 4 packed values stored locally AND to the peer
// via st.async carrying tx bytes to the peer's ping-pong mbarrier; sync =
// one expect_tx(4096) by tid0 + __syncthreads + parity try_wait. Addressing
// identical to R10 (validated correct); only the sync mechanism differs.
// ============================================================================
#define SXP 260
#define S2_OFF_W    0                         // local 64 W rows: hi 16KB + lo 16KB
#define S2_OFF_AT   32768                     // AT + buf*8192 + hilo*4096 (16KB)
#define S2_OFF_SX   49152                     // 16 x SXP ints (16640 B)
#define S2_OFF_MBAR (S2_OFF_SX + 16 * SXP * 4)
#define S2_SMEM     (S2_OFF_MBAR + 64)

__global__ void __launch_bounds__(256, 1) __cluster_dims__(2, 1, 1)
k_rnn_cluster(const int* __restrict__ x)
{
    extern __shared__ __align__(16) char sm[];
    char* WHhi = sm + S2_OFF_W;
    char* WHlo = sm + S2_OFF_W + 16384;
    char* AT   = sm + S2_OFF_AT;
    int*  sx   = (int*)(sm + S2_OFF_SX);

    const int tid = threadIdx.x, w = tid >> 5, lane = tid & 31;
    const uint32_t rank = my_cluster_rank();
    const uint32_t peer = rank ^ 1;
    const int b0 = (blockIdx.x >> 1) * 16;
    const uint32_t mbar0 = smem_u32(sm) + S2_OFF_MBAR;
    const uint32_t mbar1 = mbar0 + 8;

    // prologue: local W half, x stage, zero h buffer 0, mbar init
    load_tile(g_WHhi + (long long)rank * 64 * 128, WHhi, 64, tid);
    load_tile(g_WHlo + (long long)rank * 64 * 128, WHlo, 64, tid);
    for (int i = tid; i < 16 * SEQ; i += 256) {
        int row = i >> 8, t = i & 255;
        sx[row * SXP + t] = x[(b0 + row) * SEQ + t];
    }
    for (int i = tid; i < 512; i += 256)
        ((uint4*)AT)[i] = make_uint4(0, 0, 0, 0);
    if (tid == 0) { MBAR_INIT(mbar0, 1); MBAR_INIT(mbar1, 1); }
    __syncthreads();

    // preload B fragments (W_hh local rows w*8..w*8+8, full K) — static
    const int l15 = lane & 15;
    const int browB = w * 8 + (l15 & 7);
    const int bkhB  = (l15 >> 3) & 1;
    const int swB   = l15 & 7;
    const uint32_t sBh = smem_u32(WHhi) + browB * 256;
    const uint32_t sBl = smem_u32(WHlo) + browB * 256;
    uint32_t bfh[8][2], bfl[8][2];
    #pragma unroll
    for (int ks = 0; ks < 8; ks++) {
        const uint32_t uB = (uint32_t)(((2 * ks + bkhB) ^ swB) << 4);
        ldmx2(bfh[ks], sBh + uB);
        ldmx2(bfl[ks], sBl + uB);
    }

    // A-frag addressing
    const int arow = lane & 15;
    const int akh  = lane >> 4;
    const int swA  = lane & 7;
    const uint32_t sAT = smem_u32(AT);
    const uint32_t aH0 = sAT + arow * 256;

    // epilogue addressing: thread owns rows g, g+8; cols jc = rank*64+w*8+2*tig
    const int g = lane >> 2, tig = lane & 3;
    const int jc = (int)rank * 64 + w * 8 + 2 * tig;
    const int ustore = (int)rank * 8 + w;
    const uint32_t st0 = (uint32_t)(g * 256 + ((ustore ^ (g & 7)) << 4) + 4 * tig);
    const uint32_t st1 = (uint32_t)((g + 8) * 256 + ((ustore ^ ((g + 8) & 7)) << 4) + 4 * tig);

    // mbar init on both CTAs must complete before any remote traffic
    CLUSTER_SYNC();
    const uint32_t peerAT    = mapa_peer(sAT, peer);
    const uint32_t peerMbar0 = mapa_peer(mbar0, peer);
    const uint32_t peerMbar1 = mapa_peer(mbar1, peer);

    int cur = 0;
    for (int t = 0; t < SEQ; t++) {
        const uint32_t myMbar = (t & 1) ? mbar1 : mbar0;
        const uint32_t pMbar  = (t & 1) ? peerMbar1 : peerMbar0;
        if (tid == 0) MBAR_EXPECT_TX(myMbar, 4096);

        // P gather (consumed post-MMA; L2 latency hides under MMA)
        const int idx0 = sx[g * SXP + t];
        const int idx1 = sx[(g + 8) * SXP + t];
        const float2 p0 = *(const float2*)(g_P + idx0 * HID + jc);
        const float2 p1 = *(const float2*)(g_P + idx1 * HID + jc);

        float aH[4] = {0, 0, 0, 0}, aM[4] = {0, 0, 0, 0}, aL[4] = {0, 0, 0, 0};
        const uint32_t aAddrH = aH0 + cur * 8192;
        const uint32_t aAddrL = aAddrH + 4096;
        #pragma unroll
        for (int ks = 0; ks < 8; ks++) {
            const uint32_t uA = (uint32_t)(((2 * ks + akh) ^ swA) << 4);
            uint32_t ahi[4], alo[4];
            ldmx4(ahi, aAddrH + uA);
            ldmx4(alo, aAddrL + uA);
            mma_f16(aH, ahi, bfh[ks][0], bfh[ks][1]);
            mma_f16(aM, ahi, bfl[ks][0], bfl[ks][1]);
            mma_f16(aL, alo, bfh[ks][0], bfh[ks][1]);
        }

        // epilogue: v = mma + P; h = tanh(v); split; store local + peer (st.async)
        const int nxt = cur ^ 1;
        char* DhiL = AT + nxt * 8192;
        char* DloL = DhiL + 4096;
        const uint32_t DhiR = peerAT + nxt * 8192;
        const uint32_t DloR = DhiR + 4096;
        const float h00 = fast_tanh(aH[0] + aM[0] + aL[0] + p0.x);
        const float h01 = fast_tanh(aH[1] + aM[1] + aL[1] + p0.y);
        const float h10 = fast_tanh(aH[2] + aM[2] + aL[2] + p1.x);
        const float h11 = fast_tanh(aH[3] + aM[3] + aL[3] + p1.y);
        uint32_t lo0, lo1;
        const uint32_t hi0 = pack_hi(h00, h01, lo0);
        const uint32_t hi1 = pack_hi(h10, h11, lo1);
        *(uint32_t*)(DhiL + st0) = hi0;
        *(uint32_t*)(DhiL + st1) = hi1;
        *(uint32_t*)(DloL + st0) = lo0;
        *(uint32_t*)(DloL + st1) = lo1;
        ST_ASYNC_U32(DhiR + st0, hi0, pMbar);
        ST_ASYNC_U32(DhiR + st1, hi1, pMbar);
        ST_ASYNC_U32(DloR + st0, lo0, pMbar);
        ST_ASYNC_U32(DloR + st1, lo1, pMbar);

        __syncthreads();                          // local half visible
        mbar_wait_acq(myMbar, (uint32_t)((t >> 1) & 1));   // remote half arrived
        cur = nxt;
    }

    // write final h (full 128 cols present locally) — rank 0 only
    if (rank == 0) {
        char* Fhi = AT + cur * 8192;
        char* Flo = AT + cur * 8192 + 4096;
        for (int i = tid; i < 16 * 64; i += 256) {
            const int row = i >> 6, cp = i & 63;
            const uint32_t off = (uint32_t)(row * 256 + (((cp >> 2) ^ (row & 7)) << 4) + (cp & 3) * 4);
            ((uint32_t*)g_Hhi)[(b0 + row) * 64 + cp] = *(const uint32_t*)(Fhi + off);
            ((uint32_t*)g_Hlo)[(b0 + row) * 64 + cp] = *(const uint32_t*)(Flo + off);
        }
    }
    CLUSTER_SYNC();   // no CTA exits while peer traffic may be in flight
}

// ============================================================================
// launch
// ============================================================================
extern "C" void kernel_launch(void* const* d_in, const int* in_sizes, int n_in,
                              void* d_out, int out_size) {
    const int*   x    = (const int*)d_in[0];     // int32: JAX downcasts int64
    const float* emb  = (const float*)d_in[1];
    const float* W_ih = (const float*)d_in[2];
    const float* W_hh = (const float*)d_in[3];
    const float* b_ih = (const float*)d_in[4];
    const float* b_hh = (const float*)d_in[5];
    const float* W_fc = (const float*)d_in[6];
    const float* b_fc = (const float*)d_in[7];
    float*       out  = (float*)d_out;

    static float* P_p = nullptr;
    static __half *Ehi_p, *Elo_p, *Whi_p, *IHhi_p, *IHlo_p;
    static __half *WHhi_p, *WHlo_p, *Hhi_p, *Hlo_p;
    if (!P_p) {
        cudaGetSymbolAddress((void**)&P_p,    g_P);
        cudaGetSymbolAddress((void**)&Ehi_p,  g_Ehi);
        cudaGetSymbolAddress((void**)&Elo_p,  g_Elo);
        cudaGetSymbolAddress((void**)&Whi_p,  g_Whi);
        cudaGetSymbolAddress((void**)&IHhi_p, g_IHhi);
        cudaGetSymbolAddress((void**)&IHlo_p, g_IHlo);
        cudaGetSymbolAddress((void**)&WHhi_p, g_WHhi);
        cudaGetSymbolAddress((void**)&WHlo_p, g_WHlo);
        cudaGetSymbolAddress((void**)&Hhi_p,  g_Hhi);
        cudaGetSymbolAddress((void**)&Hlo_p,  g_Hlo);
        cudaFuncSetAttribute(k_gemm,        cudaFuncAttributeMaxDynamicSharedMemorySize, GEMM_SMEM);
        cudaFuncSetAttribute(k_head,        cudaFuncAttributeMaxDynamicSharedMemorySize, HD_SMEM);
        cudaFuncSetAttribute(k_rnn_cluster, cudaFuncAttributeMaxDynamicSharedMemorySize, S2_SMEM);
    }

    // pre-split to hi/lo fp16 (K padded to 128); W_fc needs hi only
    k_cvt<<<VOCAB / 8, 256>>>(emb,  EMBED, Ehi_p,  Elo_p);
    k_cvt<<<HID / 8,   256>>>(W_ih, EMBED, IHhi_p, IHlo_p);
    k_cvt<<<HID / 8,   256>>>(W_hh, HID,   WHhi_p, WHlo_p);
    k_cvt_hi<<<VOCAB / 8, 256>>>(W_fc, HID, Whi_p);

    // P[v][j] = emb[v]·W_ih[j] + (b_ih+b_hh)[j]  (3-term: P near-fp32)
    k_gemm<<<dim3(VOCAB / 128, HID / 64), 256, GEMM_SMEM>>>(
        Ehi_p, Elo_p, IHhi_p, IHlo_p, P_p, HID, b_ih, b_hh);

    // recurrent scan: cluster-of-2 on 128 SMs, st.async tx-count sync
    k_rnn_cluster<<<BATCH / 8, 256, S2_SMEM>>>(x);

    // head: persistent-strip single-term fp16
    k_head<<<dim3(BATCH / 128, VOCAB / (NT_STRIP * 64)), 256, HD_SMEM>>>(
        Hhi_p, Whi_p, out, b_fc);
}

// round 14
// speedup vs baseline: 1.8907x; 1.1913x over previous
#include <cuda_runtime.h>
#include <cuda_fp16.h>
#include <cstdint>

// Problem constants
#define VOCAB  32000
#define EMBED  100
#define HID    128
#define BATCH  1024
#define SEQ    256

// -------- device scratch (no allocation allowed) --------
__device__ __align__(16) float g_P[VOCAB * HID];        // fused projections (16.4 MB)
__device__ __align__(16) __half g_Ehi[VOCAB * 128];     // emb split (padded K=128)
__device__ __align__(16) __half g_Elo[VOCAB * 128];
__device__ __align__(16) __half g_Whi[VOCAB * 128];     // W_fc hi (head is single-term)
__device__ __align__(16) __half g_IHhi[128 * 128];      // W_ih split
__device__ __align__(16) __half g_IHlo[128 * 128];
__device__ __align__(16) __half g_WHhi[128 * 128];      // W_hh split
__device__ __align__(16) __half g_WHlo[128 * 128];
__device__ __align__(16) __half g_Hhi[BATCH * 128];     // h_last (fp16)

// ============================================================================
// Pre-split conversion: fp32 [rows][Kv] -> hi/lo fp16 [rows][128] (zero-pad).
// ============================================================================
__global__ void __launch_bounds__(256) k_cvt(
    const float* __restrict__ src, int Kv,
    __half* __restrict__ hi, __half* __restrict__ lo)
{
    const int r    = blockIdx.x * 8 + (threadIdx.x >> 5);
    const int lane = threadIdx.x & 31;
    #pragma unroll
    for (int cp = lane; cp < 64; cp += 32) {
        const int c0 = 2 * cp;
        float a = (c0     < Kv) ? src[(long long)r * Kv + c0]     : 0.0f;
        float b = (c0 + 1 < Kv) ? src[(long long)r * Kv + c0 + 1] : 0.0f;
        __half ha = __float2half_rn(a), hb = __float2half_rn(b);
        __half la = __float2half_rn(a - __half2float(ha));
        __half lb = __float2half_rn(b - __half2float(hb));
        ((uint32_t*)hi)[r * 64 + cp] = (uint32_t)*(uint16_t*)&ha | ((uint32_t)*(uint16_t*)&hb << 16);
        ((uint32_t*)lo)[r * 64 + cp] = (uint32_t)*(uint16_t*)&la | ((uint32_t)*(uint16_t*)&lb << 16);
    }
}
// hi-only variant (head never reads W_fc lo)
__global__ void __launch_bounds__(256) k_cvt_hi(
    const float* __restrict__ src, int Kv, __half* __restrict__ hi)
{
    const int r    = blockIdx.x * 8 + (threadIdx.x >> 5);
    const int lane = threadIdx.x & 31;
    #pragma unroll
    for (int cp = lane; cp < 64; cp += 32) {
        const int c0 = 2 * cp;
        float a = (c0     < Kv) ? src[(long long)r * Kv + c0]     : 0.0f;
        float b = (c0 + 1 < Kv) ? src[(long long)r * Kv + c0 + 1] : 0.0f;
        __half ha = __float2half_rn(a), hb = __float2half_rn(b);
        ((uint32_t*)hi)[r * 64 + cp] = (uint32_t)*(uint16_t*)&ha | ((uint32_t)*(uint16_t*)&hb << 16);
    }
}

// ============================================================================
// mma.sync helpers (fp16 in / fp32 accum)
// ============================================================================
__device__ __forceinline__ uint32_t smem_u32(const void* p) {
    uint32_t a;
    asm("{ .reg .u64 t; cvta.to.shared.u64 t, %1; cvt.u32.u64 %0, t; }" : "=r"(a) : "l"(p));
    return a;
}
__device__ __forceinline__ void ldmx4(uint32_t* r, uint32_t a) {
    asm volatile("ldmatrix.sync.aligned.m8n8.x4.shared.b16 {%0,%1,%2,%3}, [%4];"
                 : "=r"(r[0]), "=r"(r[1]), "=r"(r[2]), "=r"(r[3]) : "r"(a));
}
__device__ __forceinline__ void ldmx2(uint32_t* r, uint32_t a) {
    asm volatile("ldmatrix.sync.aligned.m8n8.x2.shared.b16 {%0,%1}, [%2];"
                 : "=r"(r[0]), "=r"(r[1]) : "r"(a));
}
__device__ __forceinline__ void mma_f16(float* c, const uint32_t* a,
                                        uint32_t b0, uint32_t b1) {
    asm volatile("mma.sync.aligned.m16n8k16.row.col.f32.f16.f16.f32 "
                 "{%0,%1,%2,%3}, {%4,%5,%6,%7}, {%8,%9}, {%0,%1,%2,%3};"
                 : "+f"(c[0]), "+f"(c[1]), "+f"(c[2]), "+f"(c[3])
                 : "r"(a[0]), "r"(a[1]), "r"(a[2]), "r"(a[3]), "r"(b0), "r"(b1));
}
__device__ __forceinline__ uint32_t tswz(int row, int u) {
    return (uint32_t)(row * 256 + ((u ^ (row & 7)) << 4));
}
__device__ __forceinline__ void load_tile(const __half* __restrict__ g,
                                          char* s, int rows, int tid) {
    #pragma unroll 4
    for (int i = tid; i < rows * 16; i += 256) {
        int row = i >> 4, u = i & 15;
        *(uint4*)(s + tswz(row, u)) = *(const uint4*)(g + (long long)row * 128 + u * 8);
    }
}
__device__ __forceinline__ float fast_tanh(float x) {
    float e = __expf(2.0f * x);
    return 1.0f - __fdividef(2.0f, e + 1.0f);
}
__device__ __forceinline__ uint32_t pack_h2(float a, float b) {
    __half ha = __float2half_rn(a), hb = __float2half_rn(b);
    return (uint32_t)*(uint16_t*)&ha | ((uint32_t)*(uint16_t*)&hb << 16);
}
__device__ __forceinline__ uint32_t mapa_peer(uint32_t addr, uint32_t rank) {
    uint32_t r;
    asm("mapa.shared::cluster.u32 %0, %1, %2;" : "=r"(r) : "r"(addr), "r"(rank));
    return r;
}
__device__ __forceinline__ uint32_t my_cluster_rank() {
    uint32_t r;
    asm("mov.u32 %0, %%cluster_ctarank;" : "=r"(r));
    return r;
}
#define CLUSTER_SYNC() do { \
    asm volatile("barrier.cluster.arrive.aligned;" ::: "memory"); \
    asm volatile("barrier.cluster.wait.aligned;" ::: "memory"); } while (0)
#define MBAR_INIT(a, c) \
    asm volatile("mbarrier.init.shared.b64 [%0], %1;" :: "r"(a), "r"(c) : "memory")
#define MBAR_EXPECT_TX(a, bytes) \
    asm volatile("mbarrier.arrive.expect_tx.shared.b64 _, [%0], %1;" :: "r"(a), "r"(bytes) : "memory")
#define ST_ASYNC_U32(raddr, val, rmbar) \
    asm volatile("st.async.weak.shared::cluster.mbarrier::complete_tx::bytes.b32 [%0], %1, [%2];" \
                 :: "r"(raddr), "r"(val), "r"(rmbar) : "memory")
__device__ __forceinline__ void mbar_wait_acq(uint32_t mbar, uint32_t parity) {
    uint32_t done;
    asm volatile("{\n\t.reg .pred p;\n\t"
                 "mbarrier.try_wait.parity.acquire.cluster.shared::cta.b64 p, [%1], %2;\n\t"
                 "selp.b32 %0, 1, 0, p;\n\t}" : "=r"(done) : "r"(mbar), "r"(parity) : "memory");
    if (!done) {
        asm volatile("{\n\t.reg .pred P1;\n\tWL%=:\n\t"
                     "mbarrier.try_wait.parity.acquire.cluster.shared::cta.b64 P1, [%0], %1;\n\t"
                     "@P1 bra.uni WD%=;\n\tbra.uni WL%=;\n\tWD%=:\n\t}"
                     :: "r"(mbar), "r"(parity) : "memory");
    }
}
#define CP_ASYNC16(dst, src) \
    asm volatile("cp.async.cg.shared.global [%0], [%1], 16;" :: "r"(dst), "l"(src) : "memory")
#define CP_COMMIT() asm volatile("cp.async.commit_group;" ::: "memory")
#define CP_WAIT0()  asm volatile("cp.async.wait_group 0;" ::: "memory")

// ============================================================================
// k_gemm: 3-term split GEMM (P projection). Unchanged from passing R11-13.
// ============================================================================
#define A_TILE 32768
#define B_TILE 16384
#define GEMM_SMEM (2 * A_TILE + 2 * B_TILE)   // 98304
#define EPAD 68

__global__ void __launch_bounds__(256, 2) k_gemm(
    const __half* __restrict__ Ahi_g, const __half* __restrict__ Alo_g,
    const __half* __restrict__ Bhi_g, const __half* __restrict__ Blo_g,
    float* __restrict__ out, long long ldout,
    const float* __restrict__ bias1, const float* __restrict__ bias2)
{
    extern __shared__ __align__(16) char sm[];
    __shared__ float sbias[64];
    char* Ahi = sm;
    char* Alo = sm + A_TILE;
    char* Bhi = sm + 2 * A_TILE;
    char* Blo = sm + 2 * A_TILE + B_TILE;

    const int tid = threadIdx.x, w = tid >> 5, lane = tid & 31;
    const int wm = w >> 1, wn = w & 1;
    const int m0 = blockIdx.x * 128, n0 = blockIdx.y * 64;

    load_tile(Ahi_g + (long long)m0 * 128, Ahi, 128, tid);
    load_tile(Alo_g + (long long)m0 * 128, Alo, 128, tid);
    load_tile(Bhi_g + (long long)n0 * 128, Bhi, 64, tid);
    load_tile(Blo_g + (long long)n0 * 128, Blo, 64, tid);
    if (tid < 64) sbias[tid] = bias1[n0 + tid] + (bias2 ? bias2[n0 + tid] : 0.0f);
    __syncthreads();

    const int sw = lane & 7;
    const int arow = wm * 32 + (lane & 15);
    const int akh  = lane >> 4;
    const int brow = wn * 32 + (lane & 7) + 8 * (lane >> 4);
    const int bkh  = (lane >> 3) & 1;

    const uint32_t sA0h = smem_u32(Ahi) + arow * 256;
    const uint32_t sA0l = smem_u32(Alo) + arow * 256;
    const uint32_t sB0h = smem_u32(Bhi) + brow * 256;
    const uint32_t sB0l = smem_u32(Blo) + brow * 256;

    float acc[2][4][4];
    #pragma unroll
    for (int mt = 0; mt < 2; mt++)
        #pragma unroll
        for (int nt = 0; nt < 4; nt++)
            #pragma unroll
            for (int q = 0; q < 4; q++) acc[mt][nt][q] = 0.0f;

    #pragma unroll
    for (int ks = 0; ks < 8; ks++) {
        const uint32_t uA = (uint32_t)(((2 * ks + akh) ^ sw) << 4);
        const uint32_t uB = (uint32_t)(((2 * ks + bkh) ^ sw) << 4);
        uint32_t aHi[2][4], aLo[2][4];
        ldmx4(aHi[0], sA0h + uA);
        ldmx4(aHi[1], sA0h + 16 * 256 + uA);
        ldmx4(aLo[0], sA0l + uA);
        ldmx4(aLo[1], sA0l + 16 * 256 + uA);
        #pragma unroll
        for (int np = 0; np < 2; np++) {
            uint32_t bh[4], bl[4];
            ldmx4(bh, sB0h + np * 16 * 256 + uB);
            ldmx4(bl, sB0l + np * 16 * 256 + uB);
            #pragma unroll
            for (int mt = 0; mt < 2; mt++) {
                mma_f16(acc[mt][2 * np],     aHi[mt], bh[0], bh[1]);
                mma_f16(acc[mt][2 * np + 1], aHi[mt], bh[2], bh[3]);
                mma_f16(acc[mt][2 * np],     aLo[mt], bh[0], bh[1]);
                mma_f16(acc[mt][2 * np + 1], aLo[mt], bh[2], bh[3]);
                mma_f16(acc[mt][2 * np],     aHi[mt], bl[0], bl[1]);
                mma_f16(acc[mt][2 * np + 1], aHi[mt], bl[2], bl[3]);
            }
        }
    }

    __syncthreads();
    float* stg = (float*)sm;
    const int g = lane >> 2, tig = lane & 3;
    #pragma unroll
    for (int mt = 0; mt < 2; mt++) {
        const int r0 = wm * 32 + mt * 16 + g;
        #pragma unroll
        for (int nt = 0; nt < 4; nt++) {
            const int col = wn * 32 + nt * 8 + 2 * tig;
            *(float2*)(stg + r0 * EPAD + col)       = make_float2(acc[mt][nt][0], acc[mt][nt][1]);
            *(float2*)(stg + (r0 + 8) * EPAD + col) = make_float2(acc[mt][nt][2], acc[mt][nt][3]);
        }
    }
    __syncthreads();
    #pragma unroll 4
    for (int i = tid; i < 128 * 16; i += 256) {
        const int row = i >> 4, u = i & 15, col = u * 4;
        float4 v = *(const float4*)(stg + row * EPAD + col);
        v.x += sbias[col]; v.y += sbias[col + 1]; v.z += sbias[col + 2]; v.w += sbias[col + 3];
        *(float4*)(out + (long long)(m0 + row) * ldout + n0 + col) = v;
    }
}

// ============================================================================
// k_head: persistent-strip single-term fp16 head GEMM (unchanged from R12/13).
// ============================================================================
#define NT_STRIP 10
#define HD_SMEM (A_TILE + 2 * B_TILE + NT_STRIP * 64 * 4)

__global__ void __launch_bounds__(256, 2) k_head(
    const __half* __restrict__ Ahi_g, const __half* __restrict__ Bhi_g,
    float* __restrict__ out, const float* __restrict__ bias)
{
    extern __shared__ __align__(16) char sm[];
    char* A  = sm;
    char* Bb = sm + A_TILE;
    float* sbias = (float*)(sm + A_TILE + 2 * B_TILE);

    const int tid = threadIdx.x, w = tid >> 5, lane = tid & 31;
    const int wm = w >> 1, wn = w & 1;
    const int m0 = blockIdx.x * 128;
    const int nbase = blockIdx.y * (NT_STRIP * 64);

    {
        const __half* Ag = Ahi_g + (long long)m0 * 128;
        #pragma unroll 2
        for (int i = tid; i < 128 * 16; i += 256) {
            int row = i >> 4, u = i & 15;
            CP_ASYNC16(smem_u32(A + tswz(row, u)), Ag + (long long)row * 128 + u * 8);
        }
        const __half* Bg = Bhi_g + (long long)nbase * 128;
        for (int i = tid; i < 64 * 16; i += 256) {
            int row = i >> 4, u = i & 15;
            CP_ASYNC16(smem_u32(Bb + tswz(row, u)), Bg + (long long)row * 128 + u * 8);
        }
        CP_COMMIT();
        for (int i = tid; i < NT_STRIP * 64; i += 256) sbias[i] = bias[nbase + i];
        CP_WAIT0();
        __syncthreads();
    }

    const int sw = lane & 7;
    const int arow = wm * 32 + (lane & 15);
    const int akh  = lane >> 4;
    const int brow = wn * 32 + (lane & 7) + 8 * (lane >> 4);
    const int bkh  = (lane >> 3) & 1;
    const uint32_t sA0 = smem_u32(A) + arow * 256;
    const int g = lane >> 2, tig = lane & 3;

    int buf = 0;
    for (int ti = 0; ti < NT_STRIP; ti++) {
        if (ti < NT_STRIP - 1) {
            const __half* Bg = Bhi_g + (long long)(nbase + (ti + 1) * 64) * 128;
            char* Bn = Bb + (buf ^ 1) * B_TILE;
            for (int i = tid; i < 64 * 16; i += 256) {
                int row = i >> 4, u = i & 15;
                CP_ASYNC16(smem_u32(Bn + tswz(row, u)), Bg + (long long)row * 128 + u * 8);
            }
            CP_COMMIT();
        }

        const uint32_t sB0 = smem_u32(Bb + buf * B_TILE) + brow * 256;
        float acc[2][4][4];
        #pragma unroll
        for (int mt = 0; mt < 2; mt++)
            #pragma unroll
            for (int nt = 0; nt < 4; nt++)
                #pragma unroll
                for (int q = 0; q < 4; q++) acc[mt][nt][q] = 0.0f;

        #pragma unroll
        for (int ks = 0; ks < 8; ks++) {
            const uint32_t uA = (uint32_t)(((2 * ks + akh) ^ sw) << 4);
            const uint32_t uB = (uint32_t)(((2 * ks + bkh) ^ sw) << 4);
            uint32_t aHi[2][4];
            ldmx4(aHi[0], sA0 + uA);
            ldmx4(aHi[1], sA0 + 16 * 256 + uA);
            #pragma unroll
            for (int np = 0; np < 2; np++) {
                uint32_t bh[4];
                ldmx4(bh, sB0 + np * 16 * 256 + uB);
                #pragma unroll
                for (int mt = 0; mt < 2; mt++) {
                    mma_f16(acc[mt][2 * np],     aHi[mt], bh[0], bh[1]);
                    mma_f16(acc[mt][2 * np + 1], aHi[mt], bh[2], bh[3]);
                }
            }
        }

        const int n0 = nbase + ti * 64;
        #pragma unroll
        for (int mt = 0; mt < 2; mt++) {
            const long long r0 = (long long)(m0 + wm * 32 + mt * 16 + g) * VOCAB + n0;
            const long long r1 = r0 + 8LL * VOCAB;
            #pragma unroll
            for (int nt = 0; nt < 4; nt++) {
                const int col = wn * 32 + nt * 8 + 2 * tig;
                const float bx = sbias[ti * 64 + col], by = sbias[ti * 64 + col + 1];
                *(float2*)(out + r0 + col) = make_float2(acc[mt][nt][0] + bx, acc[mt][nt][1] + by);
                *(float2*)(out + r1 + col) = make_float2(acc[mt][nt][2] + bx, acc[mt][nt][3] + by);
            }
        }

        if (ti < NT_STRIP - 1) {
            CP_WAIT0();
            __syncthreads();
            buf ^= 1;
        }
    }
}

// ============================================================================
// Kernel B: cluster-of-2 MMA RNN scan, 2-TERM (h carried as fp16; the dropped
// h_lo term fed nothing downstream — head reads h_hi only). Per warp/step:
// 8 LDSM (A hi) + 16 HMMA (hi*Whi + hi*Wlo). h exchange via st.async with
// tx-count mbarrier sync (validated R13); tx halved to 2048.
// ============================================================================
#define SXP 260
#define S2_OFF_W    0                         // local 64 W rows: hi 16KB + lo 16KB
#define S2_OFF_AT   32768                     // A tiles: buf*4096, hi only (8KB)
#define S2_OFF_SX   40960                     // 16 x SXP ints (16640 B)
#define S2_OFF_MBAR (S2_OFF_SX + 16 * SXP * 4)
#define S2_SMEM     (S2_OFF_MBAR + 64)

__global__ void __launch_bounds__(256, 1) __cluster_dims__(2, 1, 1)
k_rnn_cluster(const int* __restrict__ x)
{
    extern __shared__ __align__(16) char sm[];
    char* WHhi = sm + S2_OFF_W;
    char* WHlo = sm + S2_OFF_W + 16384;
    char* AT   = sm + S2_OFF_AT;
    int*  sx   = (int*)(sm + S2_OFF_SX);

    const int tid = threadIdx.x, w = tid >> 5, lane = tid & 31;
    const uint32_t rank = my_cluster_rank();
    const uint32_t peer = rank ^ 1;
    const int b0 = (blockIdx.x >> 1) * 16;
    const uint32_t mbar0 = smem_u32(sm) + S2_OFF_MBAR;
    const uint32_t mbar1 = mbar0 + 8;

    // prologue: local W half, x stage, zero h buffer 0 (both bufs), mbar init
    load_tile(g_WHhi + (long long)rank * 64 * 128, WHhi, 64, tid);
    load_tile(g_WHlo + (long long)rank * 64 * 128, WHlo, 64, tid);
    for (int i = tid; i < 16 * SEQ; i += 256) {
        int row = i >> 8, t = i & 255;
        sx[row * SXP + t] = x[(b0 + row) * SEQ + t];
    }
    for (int i = tid; i < 512; i += 256)
        ((uint4*)AT)[i] = make_uint4(0, 0, 0, 0);
    if (tid == 0) { MBAR_INIT(mbar0, 1); MBAR_INIT(mbar1, 1); }
    __syncthreads();

    // preload B fragments (W_hh local rows w*8..w*8+8, full K) — static
    const int l15 = lane & 15;
    const int browB = w * 8 + (l15 & 7);
    const int bkhB  = (l15 >> 3) & 1;
    const int swB   = l15 & 7;
    const uint32_t sBh = smem_u32(WHhi) + browB * 256;
    const uint32_t sBl = smem_u32(WHlo) + browB * 256;
    uint32_t bfh[8][2], bfl[8][2];
    #pragma unroll
    for (int ks = 0; ks < 8; ks++) {
        const uint32_t uB = (uint32_t)(((2 * ks + bkhB) ^ swB) << 4);
        ldmx2(bfh[ks], sBh + uB);
        ldmx2(bfl[ks], sBl + uB);
    }

    // A-frag addressing
    const int arow = lane & 15;
    const int akh  = lane >> 4;
    const int swA  = lane & 7;
    const uint32_t sAT = smem_u32(AT);
    const uint32_t aH0 = sAT + arow * 256;

    // epilogue addressing: thread owns rows g, g+8; cols jc = rank*64+w*8+2*tig
    const int g = lane >> 2, tig = lane & 3;
    const int jc = (int)rank * 64 + w * 8 + 2 * tig;
    const int ustore = (int)rank * 8 + w;
    const uint32_t st0 = (uint32_t)(g * 256 + ((ustore ^ (g & 7)) << 4) + 4 * tig);
    const uint32_t st1 = (uint32_t)((g + 8) * 256 + ((ustore ^ ((g + 8) & 7)) << 4) + 4 * tig);

    // mbar init on both CTAs must complete before any remote traffic
    CLUSTER_SYNC();
    const uint32_t peerAT    = mapa_peer(sAT, peer);
    const uint32_t peerMbar0 = mapa_peer(mbar0, peer);
    const uint32_t peerMbar1 = mapa_peer(mbar1, peer);

    int cur = 0;
    for (int t = 0; t < SEQ; t++) {
        const uint32_t myMbar = (t & 1) ? mbar1 : mbar0;
        const uint32_t pMbar  = (t & 1) ? peerMbar1 : peerMbar0;
        if (tid == 0) MBAR_EXPECT_TX(myMbar, 2048);

        // P gather (consumed post-MMA; L2 latency hides under MMA)
        const int idx0 = sx[g * SXP + t];
        const int idx1 = sx[(g + 8) * SXP + t];
        const float2 p0 = *(const float2*)(g_P + idx0 * HID + jc);
        const float2 p1 = *(const float2*)(g_P + idx1 * HID + jc);

        float aH[4] = {0, 0, 0, 0}, aM[4] = {0, 0, 0, 0};
        const uint32_t aAddrH = aH0 + cur * 4096;
        #pragma unroll
        for (int ks = 0; ks < 8; ks++) {
            const uint32_t uA = (uint32_t)(((2 * ks + akh) ^ swA) << 4);
            uint32_t ahi[4];
            ldmx4(ahi, aAddrH + uA);
            mma_f16(aH, ahi, bfh[ks][0], bfh[ks][1]);
            mma_f16(aM, ahi, bfl[ks][0], bfl[ks][1]);
        }

        // epilogue: v = mma + P; h = tanh(v); pack fp16; store local + peer
        const int nxt = cur ^ 1;
        char* DhiL = AT + nxt * 4096;
        const uint32_t DhiR = peerAT + nxt * 4096;
        const float h00 = fast_tanh(aH[0] + aM[0] + p0.x);
        const float h01 = fast_tanh(aH[1] + aM[1] + p0.y);
        const float h10 = fast_tanh(aH[2] + aM[2] + p1.x);
        const float h11 = fast_tanh(aH[3] + aM[3] + p1.y);
        const uint32_t hi0 = pack_h2(h00, h01);
        const uint32_t hi1 = pack_h2(h10, h11);
        *(uint32_t*)(DhiL + st0) = hi0;
        *(uint32_t*)(DhiL + st1) = hi1;
        ST_ASYNC_U32(DhiR + st0, hi0, pMbar);
        ST_ASYNC_U32(DhiR + st1, hi1, pMbar);

        __syncthreads();                                   // local half visible
        mbar_wait_acq(myMbar, (uint32_t)((t >> 1) & 1));   // remote half arrived
        cur = nxt;
    }

    // write final h — rank 0 only
    if (rank == 0) {
        char* Fhi = AT + cur * 4096;
        for (int i = tid; i < 16 * 64; i += 256) {
            const int row = i >> 6, cp = i & 63;
            const uint32_t off = (uint32_t)(row * 256 + (((cp >> 2) ^ (row & 7)) << 4) + (cp & 3) * 4);
            ((uint32_t*)g_Hhi)[(b0 + row) * 64 + cp] = *(const uint32_t*)(Fhi + off);
        }
    }
    CLUSTER_SYNC();   // no CTA exits while peer traffic may be in flight
}

// ============================================================================
// launch
// ============================================================================
extern "C" void kernel_launch(void* const* d_in, const int* in_sizes, int n_in,
                              void* d_out, int out_size) {
    const int*   x    = (const int*)d_in[0];     // int32: JAX downcasts int64
    const float* emb  = (const float*)d_in[1];
    const float* W_ih = (const float*)d_in[2];
    const float* W_hh = (const float*)d_in[3];
    const float* b_ih = (const float*)d_in[4];
    const float* b_hh = (const float*)d_in[5];
    const float* W_fc = (const float*)d_in[6];
    const float* b_fc = (const float*)d_in[7];
    float*       out  = (float*)d_out;

    static float* P_p = nullptr;
    static __half *Ehi_p, *Elo_p, *Whi_p, *IHhi_p, *IHlo_p;
    static __half *WHhi_p, *WHlo_p, *Hhi_p;
    if (!P_p) {
        cudaGetSymbolAddress((void**)&P_p,    g_P);
        cudaGetSymbolAddress((void**)&Ehi_p,  g_Ehi);
        cudaGetSymbolAddress((void**)&Elo_p,  g_Elo);
        cudaGetSymbolAddress((void**)&Whi_p,  g_Whi);
        cudaGetSymbolAddress((void**)&IHhi_p, g_IHhi);
        cudaGetSymbolAddress((void**)&IHlo_p, g_IHlo);
        cudaGetSymbolAddress((void**)&WHhi_p, g_WHhi);
        cudaGetSymbolAddress((void**)&WHlo_p, g_WHlo);
        cudaGetSymbolAddress((void**)&Hhi_p,  g_Hhi);
        cudaFuncSetAttribute(k_gemm,        cudaFuncAttributeMaxDynamicSharedMemorySize, GEMM_SMEM);
        cudaFuncSetAttribute(k_head,        cudaFuncAttributeMaxDynamicSharedMemorySize, HD_SMEM);
        cudaFuncSetAttribute(k_rnn_cluster, cudaFuncAttributeMaxDynamicSharedMemorySize, S2_SMEM);
    }

    // pre-split to hi/lo fp16 (K padded to 128); W_fc needs hi only
    k_cvt<<<VOCAB / 8, 256>>>(emb,  EMBED, Ehi_p,  Elo_p);
    k_cvt<<<HID / 8,   256>>>(W_ih, EMBED, IHhi_p, IHlo_p);
    k_cvt<<<HID / 8,   256>>>(W_hh, HID,   WHhi_p, WHlo_p);
    k_cvt_hi<<<VOCAB / 8, 256>>>(W_fc, HID, Whi_p);

    // P[v][j] = emb[v]·W_ih[j] + (b_ih+b_hh)[j]  (3-term: P near-fp32)
    k_gemm<<<dim3(VOCAB / 128, HID / 64), 256, GEMM_SMEM>>>(
        Ehi_p, Elo_p, IHhi_p, IHlo_p, P_p, HID, b_ih, b_hh);

    // recurrent scan: cluster-of-2 on 128 SMs, 2-term, st.async tx sync
    k_rnn_cluster<<<BATCH / 8, 256, S2_SMEM>>>(x);

    // head: persistent-strip single-term fp16
    k_head<<<dim3(BATCH / 128, VOCAB / (NT_STRIP * 64)), 256, HD_SMEM>>>(
        Hhi_p, Whi_p, out, b_fc);
}